// round 1
// baseline (speedup 1.0000x reference)
#include <cuda_runtime.h>

// Problem constants
#define E_   1024
#define H_   16
#define D_   64
#define B_   4
#define S_   2048
#define R_   8
#define M_   (B_*S_)      // 8192 rows
#define N1_  (3*E_)       // 3072 qkv cols
#define SCALING_ 2.0f     // alpha/rank = 16/8
#define SCALE_   0.125f   // D^-0.5

// ---------------------------------------------------------------------------
// Scratch (device globals; no allocation allowed in kernel_launch)
// ---------------------------------------------------------------------------
__device__ float g_Wq[N1_ * E_];          // folded qkv weight [3072][1024]
__device__ float g_Wp[E_ * E_];           // folded proj weight [1024][1024]
__device__ float g_qkv[M_ * N1_];         // [B*S][3*E]  (q|k|v interleaved per row)
__device__ float g_attn[M_ * E_];         // attention output [B*S][E]

// ---------------------------------------------------------------------------
// Kernel 1: fold LoRA into weights.  W_eff = W + SCALING * (B @ A)
// ---------------------------------------------------------------------------
__global__ __launch_bounds__(256) void fold_lora(
    const float* __restrict__ Wqkv, const float* __restrict__ Bq, const float* __restrict__ Aq,
    const float* __restrict__ Wproj, const float* __restrict__ Bp, const float* __restrict__ Ap)
{
    int idx = blockIdx.x * 256 + threadIdx.x;
    const int n1 = N1_ * E_;
    if (idx < n1) {
        int o = idx / E_;
        int e = idx - o * E_;
        float acc = 0.f;
        #pragma unroll
        for (int r = 0; r < R_; r++) acc += Bq[o * R_ + r] * Aq[r * E_ + e];
        g_Wq[idx] = Wqkv[idx] + SCALING_ * acc;
    } else if (idx < n1 + E_ * E_) {
        int j = idx - n1;
        int o = j / E_;
        int e = j - o * E_;
        float acc = 0.f;
        #pragma unroll
        for (int r = 0; r < R_; r++) acc += Bp[o * R_ + r] * Ap[r * E_ + e];
        g_Wp[j] = Wproj[j] + SCALING_ * acc;
    }
}

// ---------------------------------------------------------------------------
// Kernel 2: SGEMM  C[M,N] = A[M,K] @ W[N,K]^T (+bias)
// 128x128 block tile, BK=8, 256 threads, 8x8 per thread (split 4+4 fragments
// so all LDS.128 reads are conflict-free), double-buffered smem.
// ---------------------------------------------------------------------------
__global__ __launch_bounds__(256) void sgemm_nt(
    const float* __restrict__ A, const float* __restrict__ W,
    const float* __restrict__ bias, float* __restrict__ C,
    int M, int N, int K)
{
    __shared__ float As[2][8][128];
    __shared__ float Bs[2][8][128];

    const int tid = threadIdx.x;
    const int lr  = tid >> 1;            // loader row 0..127
    const int lc  = (tid & 1) << 2;      // loader col 0 or 4
    const int tm4 = (tid >> 4) << 2;     // 0..60 (rows tm4..tm4+3 and tm4+64..tm4+67)
    const int tn4 = (tid & 15) << 2;     // 0..60 (cols tn4..tn4+3 and tn4+64..tn4+67)

    const float* Ab = A + (size_t)blockIdx.y * 128 * K;
    const float* Wb = W + (size_t)blockIdx.x * 128 * K;

    float acc[8][8];
    #pragma unroll
    for (int i = 0; i < 8; i++)
        #pragma unroll
        for (int j = 0; j < 8; j++) acc[i][j] = 0.f;

    // prologue: tile 0 -> buf 0
    {
        float4 a4 = *(const float4*)(Ab + (size_t)lr * K + lc);
        float4 b4 = *(const float4*)(Wb + (size_t)lr * K + lc);
        As[0][lc + 0][lr] = a4.x; As[0][lc + 1][lr] = a4.y;
        As[0][lc + 2][lr] = a4.z; As[0][lc + 3][lr] = a4.w;
        Bs[0][lc + 0][lr] = b4.x; Bs[0][lc + 1][lr] = b4.y;
        Bs[0][lc + 2][lr] = b4.z; Bs[0][lc + 3][lr] = b4.w;
    }
    __syncthreads();

    const int nkt = K >> 3;
    int buf = 0;
    for (int kt = 0; kt < nkt; kt++) {
        float4 an, bn;
        if (kt + 1 < nkt) {
            an = *(const float4*)(Ab + (size_t)lr * K + ((kt + 1) << 3) + lc);
            bn = *(const float4*)(Wb + (size_t)lr * K + ((kt + 1) << 3) + lc);
        }
        #pragma unroll
        for (int kk = 0; kk < 8; kk++) {
            float4 alo = *(const float4*)&As[buf][kk][tm4];
            float4 ahi = *(const float4*)&As[buf][kk][tm4 + 64];
            float4 blo = *(const float4*)&Bs[buf][kk][tn4];
            float4 bhi = *(const float4*)&Bs[buf][kk][tn4 + 64];
            float ar[8] = {alo.x, alo.y, alo.z, alo.w, ahi.x, ahi.y, ahi.z, ahi.w};
            float br[8] = {blo.x, blo.y, blo.z, blo.w, bhi.x, bhi.y, bhi.z, bhi.w};
            #pragma unroll
            for (int i = 0; i < 8; i++)
                #pragma unroll
                for (int j = 0; j < 8; j++) acc[i][j] += ar[i] * br[j];
        }
        if (kt + 1 < nkt) {
            buf ^= 1;
            As[buf][lc + 0][lr] = an.x; As[buf][lc + 1][lr] = an.y;
            As[buf][lc + 2][lr] = an.z; As[buf][lc + 3][lr] = an.w;
            Bs[buf][lc + 0][lr] = bn.x; Bs[buf][lc + 1][lr] = bn.y;
            Bs[buf][lc + 2][lr] = bn.z; Bs[buf][lc + 3][lr] = bn.w;
            __syncthreads();
        }
    }

    // epilogue
    const int row0 = blockIdx.y * 128;
    const int col0 = blockIdx.x * 128;
    float4 bl = make_float4(0.f, 0.f, 0.f, 0.f), bh = bl;
    if (bias) {
        bl = *(const float4*)(bias + col0 + tn4);
        bh = *(const float4*)(bias + col0 + tn4 + 64);
    }
    #pragma unroll
    for (int i = 0; i < 8; i++) {
        int r = row0 + tm4 + ((i < 4) ? i : 60 + i);
        float4 v0 = make_float4(acc[i][0] + bl.x, acc[i][1] + bl.y,
                                acc[i][2] + bl.z, acc[i][3] + bl.w);
        float4 v1 = make_float4(acc[i][4] + bh.x, acc[i][5] + bh.y,
                                acc[i][6] + bh.z, acc[i][7] + bh.w);
        *(float4*)(C + (size_t)r * N + col0 + tn4)      = v0;
        *(float4*)(C + (size_t)r * N + col0 + tn4 + 64) = v1;
    }
}

// ---------------------------------------------------------------------------
// Kernel 3: causal flash attention, fp32.
// grid = (S/64 q-tiles, B*H). block = 256 threads as 16x16 grid, each thread
// owns a 4x4 patch of the 64x64 score tile / 64x64 output tile.
// smem (dynamic, 65-float row stride to kill bank conflicts):
//   Qs[64][65], Ks[64][65], Vs[64][65], Ps[64][65]
// ---------------------------------------------------------------------------
#define FA_STRIDE 65
#define FA_SMEM   (4 * 64 * FA_STRIDE * 4)

__global__ __launch_bounds__(256) void flash_attn(const float* __restrict__ qkv,
                                                  float* __restrict__ out)
{
    extern __shared__ float sm[];
    float* Qs = sm;
    float* Ks = sm + 64 * FA_STRIDE;
    float* Vs = sm + 2 * 64 * FA_STRIDE;
    float* Ps = sm + 3 * 64 * FA_STRIDE;

    const int tid = threadIdx.x;
    const int tx  = tid & 15;       // score cols / d cols, 4 each
    const int ty  = tid >> 4;       // score rows, 4 each
    const int b   = blockIdx.y >> 4;
    const int h   = blockIdx.y & 15;
    const int q0  = blockIdx.x * 64;

    const float* qb = qkv + (size_t)(b * S_ + q0) * N1_ + h * D_;
    const float* kb = qkv + (size_t)(b * S_) * N1_ + E_ + h * D_;
    const float* vb = kb + E_;

    // load Q tile [64 rows][64 d], row-major, stride 65
    for (int i = tid; i < 1024; i += 256) {
        int r  = i >> 4;
        int dv = (i & 15) << 2;
        float4 v4 = *(const float4*)(qb + (size_t)r * N1_ + dv);
        float* d = Qs + r * FA_STRIDE + dv;
        d[0] = v4.x; d[1] = v4.y; d[2] = v4.z; d[3] = v4.w;
    }

    float o_acc[4][4];
    float m_run[4], l_run[4];
    #pragma unroll
    for (int i = 0; i < 4; i++) {
        m_run[i] = -1e30f; l_run[i] = 0.f;
        #pragma unroll
        for (int j = 0; j < 4; j++) o_acc[i][j] = 0.f;
    }

    const int ntiles = blockIdx.x + 1;   // causal: only key tiles <= query tile
    for (int t = 0; t < ntiles; t++) {
        const int k0 = t * 64;
        __syncthreads();   // protect Ks/Vs (prev PV reads) and Q store (t==0)
        for (int i = tid; i < 1024; i += 256) {
            int r  = i >> 4;
            int dv = (i & 15) << 2;
            float4 k4 = *(const float4*)(kb + (size_t)(k0 + r) * N1_ + dv);
            float4 v4 = *(const float4*)(vb + (size_t)(k0 + r) * N1_ + dv);
            float* kd = Ks + r * FA_STRIDE + dv;
            kd[0] = k4.x; kd[1] = k4.y; kd[2] = k4.z; kd[3] = k4.w;
            float* vd = Vs + r * FA_STRIDE + dv;
            vd[0] = v4.x; vd[1] = v4.y; vd[2] = v4.z; vd[3] = v4.w;
        }
        __syncthreads();

        // S = Q K^T  (4x4 per thread)
        float sc[4][4];
        #pragma unroll
        for (int i = 0; i < 4; i++)
            #pragma unroll
            for (int j = 0; j < 4; j++) sc[i][j] = 0.f;

        #pragma unroll 8
        for (int dd = 0; dd < 64; dd++) {
            float qv[4], kv[4];
            #pragma unroll
            for (int i = 0; i < 4; i++) qv[i] = Qs[(4 * ty + i) * FA_STRIDE + dd];
            #pragma unroll
            for (int j = 0; j < 4; j++) kv[j] = Ks[(4 * tx + j) * FA_STRIDE + dd];
            #pragma unroll
            for (int i = 0; i < 4; i++)
                #pragma unroll
                for (int j = 0; j < 4; j++) sc[i][j] += qv[i] * kv[j];
        }

        // scale + causal mask (only the diagonal tile needs element masking)
        const bool diag = (t == (int)blockIdx.x);
        #pragma unroll
        for (int i = 0; i < 4; i++) {
            int qrow = q0 + 4 * ty + i;
            #pragma unroll
            for (int j = 0; j < 4; j++) {
                float s = sc[i][j] * SCALE_;
                if (diag && (k0 + 4 * tx + j > qrow)) s = -1e30f;
                sc[i][j] = s;
            }
        }

        // online softmax (row stats reduced over the 16 tx threads = half warp)
        #pragma unroll
        for (int i = 0; i < 4; i++) {
            float mx = fmaxf(fmaxf(sc[i][0], sc[i][1]), fmaxf(sc[i][2], sc[i][3]));
            for (int off = 8; off >= 1; off >>= 1)
                mx = fmaxf(mx, __shfl_xor_sync(0xffffffffu, mx, off));
            float mnew = fmaxf(m_run[i], mx);
            float rs = 0.f;
            #pragma unroll
            for (int j = 0; j < 4; j++) {
                float p = __expf(sc[i][j] - mnew);
                sc[i][j] = p;
                rs += p;
            }
            for (int off = 8; off >= 1; off >>= 1)
                rs += __shfl_xor_sync(0xffffffffu, rs, off);
            float corr = __expf(m_run[i] - mnew);
            l_run[i] = l_run[i] * corr + rs;
            m_run[i] = mnew;
            #pragma unroll
            for (int j = 0; j < 4; j++) o_acc[i][j] *= corr;
            float* pd = Ps + (4 * ty + i) * FA_STRIDE + 4 * tx;
            pd[0] = sc[i][0]; pd[1] = sc[i][1]; pd[2] = sc[i][2]; pd[3] = sc[i][3];
        }
        __syncthreads();

        // O += P V
        #pragma unroll 8
        for (int k = 0; k < 64; k++) {
            float pa[4], vv[4];
            #pragma unroll
            for (int i = 0; i < 4; i++) pa[i] = Ps[(4 * ty + i) * FA_STRIDE + k];
            #pragma unroll
            for (int j = 0; j < 4; j++) vv[j] = Vs[k * FA_STRIDE + 4 * tx + j];
            #pragma unroll
            for (int i = 0; i < 4; i++)
                #pragma unroll
                for (int j = 0; j < 4; j++) o_acc[i][j] += pa[i] * vv[j];
        }
    }

    // normalize + write [B,S,E] layout directly (head h occupies cols h*64..)
    #pragma unroll
    for (int i = 0; i < 4; i++) {
        float inv = 1.0f / l_run[i];
        float* od = out + (size_t)(b * S_ + q0 + 4 * ty + i) * E_ + h * D_ + 4 * tx;
        od[0] = o_acc[i][0] * inv;
        od[1] = o_acc[i][1] * inv;
        od[2] = o_acc[i][2] * inv;
        od[3] = o_acc[i][3] * inv;
    }
}

// ---------------------------------------------------------------------------
// kernel_launch
// Inputs (metadata order): x, mask, Wqkv, Wproj, bproj, Aqkv, Bqkv, Aproj, Bproj
// mask is always causal tril -> hardcoded, unused.
// ---------------------------------------------------------------------------
extern "C" void kernel_launch(void* const* d_in, const int* in_sizes, int n_in,
                              void* d_out, int out_size)
{
    const float* x     = (const float*)d_in[0];
    const float* Wqkv  = (const float*)d_in[2];
    const float* Wproj = (const float*)d_in[3];
    const float* bproj = (const float*)d_in[4];
    const float* Aq    = (const float*)d_in[5];
    const float* Bq    = (const float*)d_in[6];
    const float* Ap    = (const float*)d_in[7];
    const float* Bp    = (const float*)d_in[8];
    float* out = (float*)d_out;

    float *wq, *wp, *qkvBuf, *attnBuf;
    cudaGetSymbolAddress((void**)&wq,      g_Wq);
    cudaGetSymbolAddress((void**)&wp,      g_Wp);
    cudaGetSymbolAddress((void**)&qkvBuf,  g_qkv);
    cudaGetSymbolAddress((void**)&attnBuf, g_attn);

    const int foldN = N1_ * E_ + E_ * E_;
    fold_lora<<<(foldN + 255) / 256, 256>>>(Wqkv, Bq, Aq, Wproj, Bp, Ap);

    // qkv = x @ Wqkv_eff^T   [8192, 3072]
    sgemm_nt<<<dim3(N1_ / 128, M_ / 128), 256>>>(x, wq, nullptr, qkvBuf, M_, N1_, E_);

    // causal flash attention -> g_attn [8192, 1024]
    cudaFuncSetAttribute(flash_attn, cudaFuncAttributeMaxDynamicSharedMemorySize, FA_SMEM);
    flash_attn<<<dim3(S_ / 64, B_ * H_), 256, FA_SMEM>>>(qkvBuf, attnBuf);

    // out = attn @ Wproj_eff^T + bproj   [8192, 1024]
    sgemm_nt<<<dim3(E_ / 128, M_ / 128), 256>>>(attnBuf, wp, bproj, out, M_, E_, E_);
}

// round 2
// speedup vs baseline: 1.0921x; 1.0921x over previous
#include <cuda_runtime.h>

// Problem constants
#define E_   1024
#define H_   16
#define D_   64
#define B_   4
#define S_   2048
#define R_   8
#define M_   (B_*S_)      // 8192 rows
#define N1_  (3*E_)       // 3072 qkv cols
#define SCALING_ 2.0f     // alpha/rank = 16/8
#define SCALE_   0.125f   // D^-0.5

// ---------------------------------------------------------------------------
// Scratch (device globals; no allocation allowed in kernel_launch)
// ---------------------------------------------------------------------------
__device__ float g_Wq[N1_ * E_];          // folded qkv weight [3072][1024]
__device__ float g_Wp[E_ * E_];           // folded proj weight [1024][1024]
__device__ float g_qkv[M_ * N1_];         // [B*S][3*E]
__device__ float g_attn[M_ * E_];         // attention output [B*S][E]

// ---------------------------------------------------------------------------
// Kernel 1: fold LoRA into weights.  W_eff = W + SCALING * (B @ A)
// ---------------------------------------------------------------------------
__global__ __launch_bounds__(256) void fold_lora(
    const float* __restrict__ Wqkv, const float* __restrict__ Bq, const float* __restrict__ Aq,
    const float* __restrict__ Wproj, const float* __restrict__ Bp, const float* __restrict__ Ap)
{
    int idx = blockIdx.x * 256 + threadIdx.x;
    const int n1 = N1_ * E_;
    if (idx < n1) {
        int o = idx / E_;
        int e = idx - o * E_;
        float acc = 0.f;
        #pragma unroll
        for (int r = 0; r < R_; r++) acc += Bq[o * R_ + r] * Aq[r * E_ + e];
        g_Wq[idx] = Wqkv[idx] + SCALING_ * acc;
    } else if (idx < n1 + E_ * E_) {
        int j = idx - n1;
        int o = j / E_;
        int e = j - o * E_;
        float acc = 0.f;
        #pragma unroll
        for (int r = 0; r < R_; r++) acc += Bp[o * R_ + r] * Ap[r * E_ + e];
        g_Wp[j] = Wproj[j] + SCALING_ * acc;
    }
}

// ---------------------------------------------------------------------------
// Kernel 2: SGEMM  C[M,N] = A[M,K] @ W[N,K]^T (+bias)   (unchanged)
// ---------------------------------------------------------------------------
__global__ __launch_bounds__(256) void sgemm_nt(
    const float* __restrict__ A, const float* __restrict__ W,
    const float* __restrict__ bias, float* __restrict__ C,
    int M, int N, int K)
{
    __shared__ float As[2][8][128];
    __shared__ float Bs[2][8][128];

    const int tid = threadIdx.x;
    const int lr  = tid >> 1;
    const int lc  = (tid & 1) << 2;
    const int tm4 = (tid >> 4) << 2;
    const int tn4 = (tid & 15) << 2;

    const float* Ab = A + (size_t)blockIdx.y * 128 * K;
    const float* Wb = W + (size_t)blockIdx.x * 128 * K;

    float acc[8][8];
    #pragma unroll
    for (int i = 0; i < 8; i++)
        #pragma unroll
        for (int j = 0; j < 8; j++) acc[i][j] = 0.f;

    {
        float4 a4 = *(const float4*)(Ab + (size_t)lr * K + lc);
        float4 b4 = *(const float4*)(Wb + (size_t)lr * K + lc);
        As[0][lc + 0][lr] = a4.x; As[0][lc + 1][lr] = a4.y;
        As[0][lc + 2][lr] = a4.z; As[0][lc + 3][lr] = a4.w;
        Bs[0][lc + 0][lr] = b4.x; Bs[0][lc + 1][lr] = b4.y;
        Bs[0][lc + 2][lr] = b4.z; Bs[0][lc + 3][lr] = b4.w;
    }
    __syncthreads();

    const int nkt = K >> 3;
    int buf = 0;
    for (int kt = 0; kt < nkt; kt++) {
        float4 an, bn;
        if (kt + 1 < nkt) {
            an = *(const float4*)(Ab + (size_t)lr * K + ((kt + 1) << 3) + lc);
            bn = *(const float4*)(Wb + (size_t)lr * K + ((kt + 1) << 3) + lc);
        }
        #pragma unroll
        for (int kk = 0; kk < 8; kk++) {
            float4 alo = *(const float4*)&As[buf][kk][tm4];
            float4 ahi = *(const float4*)&As[buf][kk][tm4 + 64];
            float4 blo = *(const float4*)&Bs[buf][kk][tn4];
            float4 bhi = *(const float4*)&Bs[buf][kk][tn4 + 64];
            float ar[8] = {alo.x, alo.y, alo.z, alo.w, ahi.x, ahi.y, ahi.z, ahi.w};
            float br[8] = {blo.x, blo.y, blo.z, blo.w, bhi.x, bhi.y, bhi.z, bhi.w};
            #pragma unroll
            for (int i = 0; i < 8; i++)
                #pragma unroll
                for (int j = 0; j < 8; j++) acc[i][j] += ar[i] * br[j];
        }
        if (kt + 1 < nkt) {
            buf ^= 1;
            As[buf][lc + 0][lr] = an.x; As[buf][lc + 1][lr] = an.y;
            As[buf][lc + 2][lr] = an.z; As[buf][lc + 3][lr] = an.w;
            Bs[buf][lc + 0][lr] = bn.x; Bs[buf][lc + 1][lr] = bn.y;
            Bs[buf][lc + 2][lr] = bn.z; Bs[buf][lc + 3][lr] = bn.w;
            __syncthreads();
        }
    }

    const int row0 = blockIdx.y * 128;
    const int col0 = blockIdx.x * 128;
    float4 bl = make_float4(0.f, 0.f, 0.f, 0.f), bh = bl;
    if (bias) {
        bl = *(const float4*)(bias + col0 + tn4);
        bh = *(const float4*)(bias + col0 + tn4 + 64);
    }
    #pragma unroll
    for (int i = 0; i < 8; i++) {
        int r = row0 + tm4 + ((i < 4) ? i : 60 + i);
        float4 v0 = make_float4(acc[i][0] + bl.x, acc[i][1] + bl.y,
                                acc[i][2] + bl.z, acc[i][3] + bl.w);
        float4 v1 = make_float4(acc[i][4] + bh.x, acc[i][5] + bh.y,
                                acc[i][6] + bh.z, acc[i][7] + bh.w);
        *(float4*)(C + (size_t)r * N + col0 + tn4)      = v0;
        *(float4*)(C + (size_t)r * N + col0 + tn4 + 64) = v1;
    }
}

// ---------------------------------------------------------------------------
// Kernel 3: causal flash attention, fp32, GEMM-style fragments.
// grid = (S/128 q-tiles, B*H), 256 threads.
// Per block: 128 q rows; iterate keys in tiles of 64.
// Per thread: 8 q rows (4 + 4 split at +64) x 4 cols -> all smem reads LDS.128.
// smem: Qt[d=64][128+4]   (Q transposed, pre-scaled)
//       Kt[d=64][64+4]    (K transposed)
//       Vs[k=64][64+4]    (V natural)
//       Pt[k=64][128+4]   (P transposed)
// ---------------------------------------------------------------------------
#define FA_BQ 128
#define FA_BK 64
#define QT_S  132
#define KT_S  68
#define PT_S  132
#define FA_SMEM ((64*QT_S + 64*KT_S + 64*KT_S + 64*PT_S) * 4)   // 102400 B

__global__ __launch_bounds__(256, 2) void flash_attn(const float* __restrict__ qkv,
                                                     float* __restrict__ out)
{
    extern __shared__ float sm[];
    float* Qt = sm;                       // [64][132]
    float* Kt = Qt + 64 * QT_S;           // [64][68]
    float* Vs = Kt + 64 * KT_S;           // [64][68]
    float* Pt = Vs + 64 * KT_S;           // [64][132]

    const int tid = threadIdx.x;
    const int tx  = tid & 15;
    const int ty  = tid >> 4;
    const int tm  = ty << 2;              // 0..60
    const int tn  = tx << 2;              // 0..60
    const int b   = blockIdx.y >> 4;
    const int h   = blockIdx.y & 15;
    const int qt  = blockIdx.x;
    const int q0  = qt * FA_BQ;

    const float* qb = qkv + (size_t)(b * S_ + q0) * N1_ + h * D_;
    const float* kb = qkv + (size_t)(b * S_) * N1_ + E_ + h * D_;
    const float* vb = kb + E_;

    // ---- load Q tile transposed + pre-scaled: Qt[d][q] = Q[q][d] * SCALE ----
    #pragma unroll
    for (int p = 0; p < 2; p++) {
        const int q4 = tm + p * 64;
        float4 r0 = *(const float4*)(qb + (size_t)(q4 + 0) * N1_ + tn);
        float4 r1 = *(const float4*)(qb + (size_t)(q4 + 1) * N1_ + tn);
        float4 r2 = *(const float4*)(qb + (size_t)(q4 + 2) * N1_ + tn);
        float4 r3 = *(const float4*)(qb + (size_t)(q4 + 3) * N1_ + tn);
        *(float4*)(Qt + (tn + 0) * QT_S + q4) =
            make_float4(r0.x * SCALE_, r1.x * SCALE_, r2.x * SCALE_, r3.x * SCALE_);
        *(float4*)(Qt + (tn + 1) * QT_S + q4) =
            make_float4(r0.y * SCALE_, r1.y * SCALE_, r2.y * SCALE_, r3.y * SCALE_);
        *(float4*)(Qt + (tn + 2) * QT_S + q4) =
            make_float4(r0.z * SCALE_, r1.z * SCALE_, r2.z * SCALE_, r3.z * SCALE_);
        *(float4*)(Qt + (tn + 3) * QT_S + q4) =
            make_float4(r0.w * SCALE_, r1.w * SCALE_, r2.w * SCALE_, r3.w * SCALE_);
    }

    float o[8][4], m[8], l[8];
    #pragma unroll
    for (int i = 0; i < 8; i++) {
        m[i] = -1e30f; l[i] = 0.f;
        #pragma unroll
        for (int j = 0; j < 4; j++) o[i][j] = 0.f;
    }

    const int ntiles = 2 * qt + 2;
    for (int t = 0; t < ntiles; t++) {
        const int k0 = t * FA_BK;
        __syncthreads();   // prev iter done with Kt/Vs/Pt; Q store visible (t==0)

        // ---- load K tile transposed + V tile natural ----
        {
            float4 r0 = *(const float4*)(kb + (size_t)(k0 + tm + 0) * N1_ + tn);
            float4 r1 = *(const float4*)(kb + (size_t)(k0 + tm + 1) * N1_ + tn);
            float4 r2 = *(const float4*)(kb + (size_t)(k0 + tm + 2) * N1_ + tn);
            float4 r3 = *(const float4*)(kb + (size_t)(k0 + tm + 3) * N1_ + tn);
            *(float4*)(Kt + (tn + 0) * KT_S + tm) = make_float4(r0.x, r1.x, r2.x, r3.x);
            *(float4*)(Kt + (tn + 1) * KT_S + tm) = make_float4(r0.y, r1.y, r2.y, r3.y);
            *(float4*)(Kt + (tn + 2) * KT_S + tm) = make_float4(r0.z, r1.z, r2.z, r3.z);
            *(float4*)(Kt + (tn + 3) * KT_S + tm) = make_float4(r0.w, r1.w, r2.w, r3.w);
            #pragma unroll
            for (int j = 0; j < 4; j++) {
                float4 v4 = *(const float4*)(vb + (size_t)(k0 + tm + j) * N1_ + tn);
                *(float4*)(Vs + (tm + j) * KT_S + tn) = v4;
            }
        }
        __syncthreads();

        // ---- S = (Q*SCALE) K^T : 8x4 per thread ----
        float sc[8][4];
        #pragma unroll
        for (int i = 0; i < 8; i++)
            #pragma unroll
            for (int j = 0; j < 4; j++) sc[i][j] = 0.f;

        #pragma unroll 8
        for (int dd = 0; dd < 64; dd++) {
            float4 qlo = *(const float4*)(Qt + dd * QT_S + tm);
            float4 qhi = *(const float4*)(Qt + dd * QT_S + tm + 64);
            float4 kv  = *(const float4*)(Kt + dd * KT_S + tn);
            float qr[8] = {qlo.x, qlo.y, qlo.z, qlo.w, qhi.x, qhi.y, qhi.z, qhi.w};
            float kr[4] = {kv.x, kv.y, kv.z, kv.w};
            #pragma unroll
            for (int i = 0; i < 8; i++)
                #pragma unroll
                for (int j = 0; j < 4; j++) sc[i][j] += qr[i] * kr[j];
        }

        // ---- causal mask (only tiles overlapping the diagonal) ----
        if (t >= 2 * qt) {
            #pragma unroll
            for (int i = 0; i < 8; i++) {
                const int qrow = q0 + tm + ((i < 4) ? i : 60 + i);
                #pragma unroll
                for (int j = 0; j < 4; j++)
                    if (k0 + tn + j > qrow) sc[i][j] = -1e30f;
            }
        }

        // ---- online softmax (row reduce over the 16 tx lanes) ----
        #pragma unroll
        for (int i = 0; i < 8; i++) {
            float mx = fmaxf(fmaxf(sc[i][0], sc[i][1]), fmaxf(sc[i][2], sc[i][3]));
            #pragma unroll
            for (int off = 8; off >= 1; off >>= 1)
                mx = fmaxf(mx, __shfl_xor_sync(0xffffffffu, mx, off));
            const float mnew = fmaxf(m[i], mx);
            float rs = 0.f;
            #pragma unroll
            for (int j = 0; j < 4; j++) {
                float p = __expf(sc[i][j] - mnew);
                sc[i][j] = p;
                rs += p;
            }
            #pragma unroll
            for (int off = 8; off >= 1; off >>= 1)
                rs += __shfl_xor_sync(0xffffffffu, rs, off);
            const float corr = __expf(m[i] - mnew);
            l[i] = l[i] * corr + rs;
            m[i] = mnew;
            #pragma unroll
            for (int j = 0; j < 4; j++) o[i][j] *= corr;
        }

        // ---- write P transposed: Pt[k][q] ----
        #pragma unroll
        for (int j = 0; j < 4; j++) {
            *(float4*)(Pt + (tn + j) * PT_S + tm) =
                make_float4(sc[0][j], sc[1][j], sc[2][j], sc[3][j]);
            *(float4*)(Pt + (tn + j) * PT_S + tm + 64) =
                make_float4(sc[4][j], sc[5][j], sc[6][j], sc[7][j]);
        }
        __syncthreads();

        // ---- O += P V : 8x4 per thread ----
        #pragma unroll 8
        for (int k = 0; k < 64; k++) {
            float4 plo = *(const float4*)(Pt + k * PT_S + tm);
            float4 phi = *(const float4*)(Pt + k * PT_S + tm + 64);
            float4 vv  = *(const float4*)(Vs + k * KT_S + tn);
            float pr[8] = {plo.x, plo.y, plo.z, plo.w, phi.x, phi.y, phi.z, phi.w};
            float vr[4] = {vv.x, vv.y, vv.z, vv.w};
            #pragma unroll
            for (int i = 0; i < 8; i++)
                #pragma unroll
                for (int j = 0; j < 4; j++) o[i][j] += pr[i] * vr[j];
        }
    }

    // ---- normalize + write [B,S,E] (head h at cols h*64..h*64+63) ----
    #pragma unroll
    for (int i = 0; i < 8; i++) {
        const int row = q0 + tm + ((i < 4) ? i : 60 + i);
        const float inv = 1.0f / l[i];
        float* od = out + (size_t)(b * S_ + row) * E_ + h * D_ + tn;
        *(float4*)od = make_float4(o[i][0] * inv, o[i][1] * inv,
                                   o[i][2] * inv, o[i][3] * inv);
    }
}

// ---------------------------------------------------------------------------
// kernel_launch
// Inputs: x, mask, Wqkv, Wproj, bproj, Aqkv, Bqkv, Aproj, Bproj
// ---------------------------------------------------------------------------
extern "C" void kernel_launch(void* const* d_in, const int* in_sizes, int n_in,
                              void* d_out, int out_size)
{
    const float* x     = (const float*)d_in[0];
    const float* Wqkv  = (const float*)d_in[2];
    const float* Wproj = (const float*)d_in[3];
    const float* bproj = (const float*)d_in[4];
    const float* Aq    = (const float*)d_in[5];
    const float* Bq    = (const float*)d_in[6];
    const float* Ap    = (const float*)d_in[7];
    const float* Bp    = (const float*)d_in[8];
    float* out = (float*)d_out;

    float *wq, *wp, *qkvBuf, *attnBuf;
    cudaGetSymbolAddress((void**)&wq,      g_Wq);
    cudaGetSymbolAddress((void**)&wp,      g_Wp);
    cudaGetSymbolAddress((void**)&qkvBuf,  g_qkv);
    cudaGetSymbolAddress((void**)&attnBuf, g_attn);

    const int foldN = N1_ * E_ + E_ * E_;
    fold_lora<<<(foldN + 255) / 256, 256>>>(Wqkv, Bq, Aq, Wproj, Bp, Ap);

    // qkv = x @ Wqkv_eff^T   [8192, 3072]
    sgemm_nt<<<dim3(N1_ / 128, M_ / 128), 256>>>(x, wq, nullptr, qkvBuf, M_, N1_, E_);

    // causal flash attention -> g_attn [8192, 1024]
    cudaFuncSetAttribute(flash_attn, cudaFuncAttributeMaxDynamicSharedMemorySize, FA_SMEM);
    flash_attn<<<dim3(S_ / FA_BQ, B_ * H_), 256, FA_SMEM>>>(qkvBuf, attnBuf);

    // out = attn @ Wproj_eff^T + bproj   [8192, 1024]
    sgemm_nt<<<dim3(E_ / 128, M_ / 128), 256>>>(attnBuf, wp, bproj, out, M_, E_, E_);
}

// round 5
// speedup vs baseline: 1.7513x; 1.6037x over previous
#include <cuda_runtime.h>
#include <cuda_bf16.h>
#include <cstdint>

// Problem constants
#define E_   1024
#define H_   16
#define D_   64
#define B_   4
#define S_   2048
#define R_   8
#define M_   (B_*S_)      // 8192
#define N1_  (3*E_)       // 3072
#define K_   1024
#define SCALING_ 2.0f
#define SCALE_   0.125f

// ---------------------------------------------------------------------------
// Scratch (device globals)
// ---------------------------------------------------------------------------
__device__ float          g_qkv[M_ * N1_];                    // fp32 qkv
__device__ __nv_bfloat16  g_xhi[M_ * E_],  g_xlo[M_ * E_];    // split x
__device__ __nv_bfloat16  g_wqhi[N1_ * E_], g_wqlo[N1_ * E_]; // split folded Wqkv
__device__ __nv_bfloat16  g_wphi[E_ * E_],  g_wplo[E_ * E_];  // split folded Wproj
__device__ __nv_bfloat16  g_ahi[M_ * E_],  g_alo[M_ * E_];    // split attn out

// ---------------------------------------------------------------------------
// PTX helpers (baseline ISA only: ldmatrix / mma.sync / cp.async)
// ---------------------------------------------------------------------------
__device__ __forceinline__ uint32_t smem_u32(const void* p) {
    uint32_t a;
    asm("{ .reg .u64 t; cvta.to.shared.u64 t, %1; cvt.u32.u64 %0, t; }" : "=r"(a) : "l"(p));
    return a;
}
__device__ __forceinline__ void cp16(uint32_t dst, const void* src) {
    asm volatile("cp.async.cg.shared.global [%0], [%1], 16;" :: "r"(dst), "l"(src));
}
__device__ __forceinline__ void cp_commit() {
    asm volatile("cp.async.commit_group;" ::: "memory");
}
template <int N>
__device__ __forceinline__ void cp_wait() {
    asm volatile("cp.async.wait_group %0;" :: "n"(N) : "memory");
}
__device__ __forceinline__ void ldsm_x4(uint32_t* r, uint32_t a) {
    asm volatile("ldmatrix.sync.aligned.m8n8.x4.shared.b16 {%0,%1,%2,%3}, [%4];"
                 : "=r"(r[0]), "=r"(r[1]), "=r"(r[2]), "=r"(r[3]) : "r"(a));
}
__device__ __forceinline__ void ldsm_x2(uint32_t* r, uint32_t a) {
    asm volatile("ldmatrix.sync.aligned.m8n8.x2.shared.b16 {%0,%1}, [%2];"
                 : "=r"(r[0]), "=r"(r[1]) : "r"(a));
}
__device__ __forceinline__ void mma16816(float* d, const uint32_t* a, const uint32_t* b) {
    asm volatile(
        "mma.sync.aligned.m16n8k16.row.col.f32.bf16.bf16.f32 "
        "{%0,%1,%2,%3}, {%4,%5,%6,%7}, {%8,%9}, {%0,%1,%2,%3};"
        : "+f"(d[0]), "+f"(d[1]), "+f"(d[2]), "+f"(d[3])
        : "r"(a[0]), "r"(a[1]), "r"(a[2]), "r"(a[3]), "r"(b[0]), "r"(b[1]));
}

// ---------------------------------------------------------------------------
// Kernel: split fp32 -> bf16 hi/lo
// ---------------------------------------------------------------------------
__global__ __launch_bounds__(256) void convert_split(const float* __restrict__ src,
                                                     __nv_bfloat16* __restrict__ hi,
                                                     __nv_bfloat16* __restrict__ lo,
                                                     int n4)
{
    int i = blockIdx.x * 256 + threadIdx.x;
    if (i >= n4) return;
    float4 v = *(const float4*)(src + i * 4);
    __nv_bfloat16 h[4], l[4];
    float vv[4] = {v.x, v.y, v.z, v.w};
    #pragma unroll
    for (int k = 0; k < 4; k++) {
        h[k] = __float2bfloat16_rn(vv[k]);
        l[k] = __float2bfloat16_rn(vv[k] - __bfloat162float(h[k]));
    }
    *(uint2*)(hi + i * 4) = *(uint2*)h;
    *(uint2*)(lo + i * 4) = *(uint2*)l;
}

// ---------------------------------------------------------------------------
// Kernel: fold LoRA into weights, output split bf16 hi/lo
// ---------------------------------------------------------------------------
__global__ __launch_bounds__(256) void fold_lora(
    const float* __restrict__ Wqkv, const float* __restrict__ Bq, const float* __restrict__ Aq,
    const float* __restrict__ Wproj, const float* __restrict__ Bp, const float* __restrict__ Ap)
{
    int idx = blockIdx.x * 256 + threadIdx.x;
    const int n1 = N1_ * E_;
    float val; __nv_bfloat16* hp; __nv_bfloat16* lp; int j;
    if (idx < n1) {
        int o = idx / E_, e = idx - o * E_;
        float acc = 0.f;
        #pragma unroll
        for (int r = 0; r < R_; r++) acc += Bq[o * R_ + r] * Aq[r * E_ + e];
        val = Wqkv[idx] + SCALING_ * acc;
        hp = g_wqhi; lp = g_wqlo; j = idx;
    } else if (idx < n1 + E_ * E_) {
        j = idx - n1;
        int o = j / E_, e = j - o * E_;
        float acc = 0.f;
        #pragma unroll
        for (int r = 0; r < R_; r++) acc += Bp[o * R_ + r] * Ap[r * E_ + e];
        val = Wproj[j] + SCALING_ * acc;
        hp = g_wphi; lp = g_wplo;
    } else return;
    __nv_bfloat16 h = __float2bfloat16_rn(val);
    hp[j] = h;
    lp[j] = __float2bfloat16_rn(val - __bfloat162float(h));
}

// ---------------------------------------------------------------------------
// Kernel: bf16x3 GEMM via mma.sync.  C = Ahi.Whi^T + Alo.Whi^T + Ahi.Wlo^T (+bias)
// CTA: 128x128 tile, 8 warps (2x4), warp tile 64x32.
// smem tiles [128 rows][40 bf16] (rows padded 32->40: 80B stride makes
// ldmatrix phases conflict-free). Double-buffered cp.async, K chunks of 32.
// ---------------------------------------------------------------------------
#define KC_      32
#define TS_      40                      // padded row length (bf16)
#define TILE_B_  (128 * TS_ * 2)         // 10240 bytes per operand tile
#define BUF_B_   (4 * TILE_B_)           // Ahi|Alo|Whi|Wlo
#define GM_SMEM  (2 * BUF_B_)            // 81920 bytes

__device__ __forceinline__ void gm_load(uint32_t bufu,
                                        const __nv_bfloat16* a0, const __nv_bfloat16* a1,
                                        const __nv_bfloat16* w0, const __nv_bfloat16* w1,
                                        int c, int tid)
{
    const __nv_bfloat16* sp[4] = {a0 + c * KC_, a1 + c * KC_, w0 + c * KC_, w1 + c * KC_};
    #pragma unroll
    for (int t = 0; t < 4; t++) {
        #pragma unroll
        for (int i = 0; i < 2; i++) {
            int idx = tid + 256 * i;           // 0..511
            int row = idx >> 2, q = idx & 3;   // 4 x 16B per row
            cp16(bufu + t * TILE_B_ + row * (TS_ * 2) + q * 16,
                 sp[t] + (size_t)row * K_ + q * 8);
        }
    }
    cp_commit();
}

__global__ __launch_bounds__(256, 2) void gemm_bf16x3(
    const __nv_bfloat16* __restrict__ Ahi, const __nv_bfloat16* __restrict__ Alo,
    const __nv_bfloat16* __restrict__ Whi, const __nv_bfloat16* __restrict__ Wlo,
    const float* __restrict__ bias, float* __restrict__ C, int N)
{
    extern __shared__ char smc[];
    const uint32_t sbase = smem_u32(smc);

    const int tid  = threadIdx.x;
    const int lane = tid & 31;
    const int warp = tid >> 5;
    const int wm   = warp >> 2;          // 0..1
    const int wn   = warp & 3;           // 0..3

    const __nv_bfloat16* a0 = Ahi + (size_t)blockIdx.y * 128 * K_;
    const __nv_bfloat16* a1 = Alo + (size_t)blockIdx.y * 128 * K_;
    const __nv_bfloat16* w0 = Whi + (size_t)blockIdx.x * 128 * K_;
    const __nv_bfloat16* w1 = Wlo + (size_t)blockIdx.x * 128 * K_;

    // ldmatrix lane byte-offsets
    const uint32_t laneA = (uint32_t)(((lane & 15) * TS_ + (lane >> 4) * 8) * 2);
    const uint32_t laneB = (uint32_t)(((lane & 7) * TS_ + ((lane >> 3) & 1) * 8) * 2);

    float acc[4][4][4];
    #pragma unroll
    for (int i = 0; i < 4; i++)
        #pragma unroll
        for (int j = 0; j < 4; j++)
            #pragma unroll
            for (int k = 0; k < 4; k++) acc[i][j][k] = 0.f;

    gm_load(sbase,          a0, a1, w0, w1, 0, tid);
    gm_load(sbase + BUF_B_, a0, a1, w0, w1, 1, tid);

    const int nchunks = K_ / KC_;        // 32
    #pragma unroll 1
    for (int c = 0; c < nchunks; c++) {
        cp_wait<1>();
        __syncthreads();

        const uint32_t bu   = sbase + (c & 1) * BUF_B_;
        const uint32_t aHiB = bu + (uint32_t)((wm * 64) * TS_ * 2) + laneA;
        const uint32_t aLoB = aHiB + TILE_B_;
        const uint32_t bHiB = bu + 2 * TILE_B_ + (uint32_t)((wn * 32) * TS_ * 2) + laneB;
        const uint32_t bLoB = bHiB + TILE_B_;

        #pragma unroll
        for (int ks = 0; ks < 2; ks++) {
            const uint32_t ko = ks * 32;           // 16 bf16 = 32 bytes
            uint32_t Bh[4][2], Bl[4][2];
            #pragma unroll
            for (int nt = 0; nt < 4; nt++) {
                ldsm_x2(Bh[nt], bHiB + nt * (8 * TS_ * 2) + ko);
                ldsm_x2(Bl[nt], bLoB + nt * (8 * TS_ * 2) + ko);
            }
            #pragma unroll
            for (int mt = 0; mt < 4; mt++) {
                uint32_t Ah[4], Al[4];
                ldsm_x4(Ah, aHiB + mt * (16 * TS_ * 2) + ko);
                ldsm_x4(Al, aLoB + mt * (16 * TS_ * 2) + ko);
                #pragma unroll
                for (int nt = 0; nt < 4; nt++) {
                    mma16816(acc[mt][nt], Ah, Bh[nt]);
                    mma16816(acc[mt][nt], Al, Bh[nt]);
                    mma16816(acc[mt][nt], Ah, Bl[nt]);
                }
            }
        }
        __syncthreads();
        if (c + 2 < nchunks)
            gm_load(sbase + (c & 1) * BUF_B_, a0, a1, w0, w1, c + 2, tid);
    }

    // epilogue: acc[mt][nt] thread layout: rows g=lane>>2 (+8), cols (lane&3)*2
    const int g  = lane >> 2;
    const int cq = (lane & 3) * 2;
    #pragma unroll
    for (int mt = 0; mt < 4; mt++) {
        const int row = blockIdx.y * 128 + wm * 64 + mt * 16 + g;
        #pragma unroll
        for (int nt = 0; nt < 4; nt++) {
            const int col = blockIdx.x * 128 + wn * 32 + nt * 8 + cq;
            float b0 = 0.f, b1 = 0.f;
            if (bias) { b0 = bias[col]; b1 = bias[col + 1]; }
            *(float2*)(C + (size_t)row * N + col) =
                make_float2(acc[mt][nt][0] + b0, acc[mt][nt][1] + b1);
            *(float2*)(C + (size_t)(row + 8) * N + col) =
                make_float2(acc[mt][nt][2] + b0, acc[mt][nt][3] + b1);
        }
    }
}

// ---------------------------------------------------------------------------
// Kernel: causal flash attention, fp32; epilogue emits split bf16 hi/lo.
// ---------------------------------------------------------------------------
#define FA_BQ 128
#define FA_BK 64
#define QT_S  132
#define KT_S  68
#define PT_S  132
#define FA_SMEM ((64*QT_S + 64*KT_S + 64*KT_S + 64*PT_S) * 4)

__global__ __launch_bounds__(256, 2) void flash_attn(const float* __restrict__ qkv)
{
    extern __shared__ float smf[];
    float* Qt = smf;
    float* Kt = Qt + 64 * QT_S;
    float* Vs = Kt + 64 * KT_S;
    float* Pt = Vs + 64 * KT_S;

    const int tid = threadIdx.x;
    const int tx  = tid & 15;
    const int ty  = tid >> 4;
    const int tm  = ty << 2;
    const int tn  = tx << 2;
    const int b   = blockIdx.y >> 4;
    const int h   = blockIdx.y & 15;
    const int qt  = blockIdx.x;
    const int q0  = qt * FA_BQ;

    const float* qb = qkv + (size_t)(b * S_ + q0) * N1_ + h * D_;
    const float* kb = qkv + (size_t)(b * S_) * N1_ + E_ + h * D_;
    const float* vb = kb + E_;

    #pragma unroll
    for (int p = 0; p < 2; p++) {
        const int q4 = tm + p * 64;
        float4 r0 = *(const float4*)(qb + (size_t)(q4 + 0) * N1_ + tn);
        float4 r1 = *(const float4*)(qb + (size_t)(q4 + 1) * N1_ + tn);
        float4 r2 = *(const float4*)(qb + (size_t)(q4 + 2) * N1_ + tn);
        float4 r3 = *(const float4*)(qb + (size_t)(q4 + 3) * N1_ + tn);
        *(float4*)(Qt + (tn + 0) * QT_S + q4) =
            make_float4(r0.x * SCALE_, r1.x * SCALE_, r2.x * SCALE_, r3.x * SCALE_);
        *(float4*)(Qt + (tn + 1) * QT_S + q4) =
            make_float4(r0.y * SCALE_, r1.y * SCALE_, r2.y * SCALE_, r3.y * SCALE_);
        *(float4*)(Qt + (tn + 2) * QT_S + q4) =
            make_float4(r0.z * SCALE_, r1.z * SCALE_, r2.z * SCALE_, r3.z * SCALE_);
        *(float4*)(Qt + (tn + 3) * QT_S + q4) =
            make_float4(r0.w * SCALE_, r1.w * SCALE_, r2.w * SCALE_, r3.w * SCALE_);
    }

    float o[8][4], m[8], l[8];
    #pragma unroll
    for (int i = 0; i < 8; i++) {
        m[i] = -1e30f; l[i] = 0.f;
        #pragma unroll
        for (int j = 0; j < 4; j++) o[i][j] = 0.f;
    }

    const int ntiles = 2 * qt + 2;
    for (int t = 0; t < ntiles; t++) {
        const int k0 = t * FA_BK;
        __syncthreads();
        {
            float4 r0 = *(const float4*)(kb + (size_t)(k0 + tm + 0) * N1_ + tn);
            float4 r1 = *(const float4*)(kb + (size_t)(k0 + tm + 1) * N1_ + tn);
            float4 r2 = *(const float4*)(kb + (size_t)(k0 + tm + 2) * N1_ + tn);
            float4 r3 = *(const float4*)(kb + (size_t)(k0 + tm + 3) * N1_ + tn);
            *(float4*)(Kt + (tn + 0) * KT_S + tm) = make_float4(r0.x, r1.x, r2.x, r3.x);
            *(float4*)(Kt + (tn + 1) * KT_S + tm) = make_float4(r0.y, r1.y, r2.y, r3.y);
            *(float4*)(Kt + (tn + 2) * KT_S + tm) = make_float4(r0.z, r1.z, r2.z, r3.z);
            *(float4*)(Kt + (tn + 3) * KT_S + tm) = make_float4(r0.w, r1.w, r2.w, r3.w);
            #pragma unroll
            for (int j = 0; j < 4; j++) {
                float4 v4 = *(const float4*)(vb + (size_t)(k0 + tm + j) * N1_ + tn);
                *(float4*)(Vs + (tm + j) * KT_S + tn) = v4;
            }
        }
        __syncthreads();

        float sc[8][4];
        #pragma unroll
        for (int i = 0; i < 8; i++)
            #pragma unroll
            for (int j = 0; j < 4; j++) sc[i][j] = 0.f;

        #pragma unroll 8
        for (int dd = 0; dd < 64; dd++) {
            float4 qlo = *(const float4*)(Qt + dd * QT_S + tm);
            float4 qhi = *(const float4*)(Qt + dd * QT_S + tm + 64);
            float4 kv  = *(const float4*)(Kt + dd * KT_S + tn);
            float qr[8] = {qlo.x, qlo.y, qlo.z, qlo.w, qhi.x, qhi.y, qhi.z, qhi.w};
            float kr[4] = {kv.x, kv.y, kv.z, kv.w};
            #pragma unroll
            for (int i = 0; i < 8; i++)
                #pragma unroll
                for (int j = 0; j < 4; j++) sc[i][j] += qr[i] * kr[j];
        }

        if (t >= 2 * qt) {
            #pragma unroll
            for (int i = 0; i < 8; i++) {
                const int qrow = q0 + tm + ((i < 4) ? i : 60 + i);
                #pragma unroll
                for (int j = 0; j < 4; j++)
                    if (k0 + tn + j > qrow) sc[i][j] = -1e30f;
            }
        }

        #pragma unroll
        for (int i = 0; i < 8; i++) {
            float mx = fmaxf(fmaxf(sc[i][0], sc[i][1]), fmaxf(sc[i][2], sc[i][3]));
            #pragma unroll
            for (int off = 8; off >= 1; off >>= 1)
                mx = fmaxf(mx, __shfl_xor_sync(0xffffffffu, mx, off));
            const float mnew = fmaxf(m[i], mx);
            float rs = 0.f;
            #pragma unroll
            for (int j = 0; j < 4; j++) {
                float p = __expf(sc[i][j] - mnew);
                sc[i][j] = p;
                rs += p;
            }
            #pragma unroll
            for (int off = 8; off >= 1; off >>= 1)
                rs += __shfl_xor_sync(0xffffffffu, rs, off);
            const float corr = __expf(m[i] - mnew);
            l[i] = l[i] * corr + rs;
            m[i] = mnew;
            #pragma unroll
            for (int j = 0; j < 4; j++) o[i][j] *= corr;
        }

        #pragma unroll
        for (int j = 0; j < 4; j++) {
            *(float4*)(Pt + (tn + j) * PT_S + tm) =
                make_float4(sc[0][j], sc[1][j], sc[2][j], sc[3][j]);
            *(float4*)(Pt + (tn + j) * PT_S + tm + 64) =
                make_float4(sc[4][j], sc[5][j], sc[6][j], sc[7][j]);
        }
        __syncthreads();

        #pragma unroll 8
        for (int k = 0; k < 64; k++) {
            float4 plo = *(const float4*)(Pt + k * PT_S + tm);
            float4 phi = *(const float4*)(Pt + k * PT_S + tm + 64);
            float4 vv  = *(const float4*)(Vs + k * KT_S + tn);
            float pr[8] = {plo.x, plo.y, plo.z, plo.w, phi.x, phi.y, phi.z, phi.w};
            float vr[4] = {vv.x, vv.y, vv.z, vv.w};
            #pragma unroll
            for (int i = 0; i < 8; i++)
                #pragma unroll
                for (int j = 0; j < 4; j++) o[i][j] += pr[i] * vr[j];
        }
    }

    #pragma unroll
    for (int i = 0; i < 8; i++) {
        const int row = q0 + tm + ((i < 4) ? i : 60 + i);
        const float inv = 1.0f / l[i];
        const size_t base = (size_t)(b * S_ + row) * E_ + h * D_ + tn;
        __nv_bfloat16 hv[4], lv[4];
        #pragma unroll
        for (int j = 0; j < 4; j++) {
            float v = o[i][j] * inv;
            hv[j] = __float2bfloat16_rn(v);
            lv[j] = __float2bfloat16_rn(v - __bfloat162float(hv[j]));
        }
        *(uint2*)(g_ahi + base) = *(uint2*)hv;
        *(uint2*)(g_alo + base) = *(uint2*)lv;
    }
}

// ---------------------------------------------------------------------------
// kernel_launch.  Inputs: x, mask, Wqkv, Wproj, bproj, Aqkv, Bqkv, Aproj, Bproj
// ---------------------------------------------------------------------------
extern "C" void kernel_launch(void* const* d_in, const int* in_sizes, int n_in,
                              void* d_out, int out_size)
{
    const float* x     = (const float*)d_in[0];
    const float* Wqkv  = (const float*)d_in[2];
    const float* Wproj = (const float*)d_in[3];
    const float* bproj = (const float*)d_in[4];
    const float* Aq    = (const float*)d_in[5];
    const float* Bq    = (const float*)d_in[6];
    const float* Ap    = (const float*)d_in[7];
    const float* Bp    = (const float*)d_in[8];
    float* out = (float*)d_out;

    float *qkvBuf;
    __nv_bfloat16 *xhi, *xlo, *wqhi, *wqlo, *wphi, *wplo, *ahi, *alo;
    cudaGetSymbolAddress((void**)&qkvBuf, g_qkv);
    cudaGetSymbolAddress((void**)&xhi,  g_xhi);  cudaGetSymbolAddress((void**)&xlo,  g_xlo);
    cudaGetSymbolAddress((void**)&wqhi, g_wqhi); cudaGetSymbolAddress((void**)&wqlo, g_wqlo);
    cudaGetSymbolAddress((void**)&wphi, g_wphi); cudaGetSymbolAddress((void**)&wplo, g_wplo);
    cudaGetSymbolAddress((void**)&ahi,  g_ahi);  cudaGetSymbolAddress((void**)&alo,  g_alo);

    convert_split<<<(M_ * E_ / 4 + 255) / 256, 256>>>(x, xhi, xlo, M_ * E_ / 4);
    const int foldN = N1_ * E_ + E_ * E_;
    fold_lora<<<(foldN + 255) / 256, 256>>>(Wqkv, Bq, Aq, Wproj, Bp, Ap);

    cudaFuncSetAttribute(gemm_bf16x3, cudaFuncAttributeMaxDynamicSharedMemorySize, GM_SMEM);
    gemm_bf16x3<<<dim3(N1_ / 128, M_ / 128), 256, GM_SMEM>>>(
        xhi, xlo, wqhi, wqlo, nullptr, qkvBuf, N1_);

    cudaFuncSetAttribute(flash_attn, cudaFuncAttributeMaxDynamicSharedMemorySize, FA_SMEM);
    flash_attn<<<dim3(S_ / FA_BQ, B_ * H_), 256, FA_SMEM>>>(qkvBuf);

    gemm_bf16x3<<<dim3(E_ / 128, M_ / 128), 256, GM_SMEM>>>(
        ahi, alo, wphi, wplo, bproj, out, E_);
}

// round 6
// speedup vs baseline: 2.7770x; 1.5857x over previous
#include <cuda_runtime.h>
#include <cuda_bf16.h>
#include <cstdint>

// Problem constants
#define E_   1024
#define H_   16
#define D_   64
#define B_   4
#define S_   2048
#define R_   8
#define M_   (B_*S_)      // 8192
#define N1_  (3*E_)       // 3072
#define K_   1024
#define SCALING_ 2.0f
#define SCALE_   0.125f

// ---------------------------------------------------------------------------
// Scratch (device globals)
// ---------------------------------------------------------------------------
__device__ __nv_bfloat16  g_qvh[M_ * N1_], g_qvl[M_ * N1_];   // split qkv (GEMM1 out)
__device__ __nv_bfloat16  g_xhi[M_ * E_],  g_xlo[M_ * E_];    // split x
__device__ __nv_bfloat16  g_wqhi[N1_ * E_], g_wqlo[N1_ * E_]; // split folded Wqkv
__device__ __nv_bfloat16  g_wphi[E_ * E_],  g_wplo[E_ * E_];  // split folded Wproj
__device__ __nv_bfloat16  g_ahi[M_ * E_],  g_alo[M_ * E_];    // split attn out

// ---------------------------------------------------------------------------
// PTX helpers (baseline ISA: ldmatrix / mma.sync / cp.async)
// ---------------------------------------------------------------------------
__device__ __forceinline__ uint32_t smem_u32(const void* p) {
    uint32_t a;
    asm("{ .reg .u64 t; cvta.to.shared.u64 t, %1; cvt.u32.u64 %0, t; }" : "=r"(a) : "l"(p));
    return a;
}
__device__ __forceinline__ void cp16(uint32_t dst, const void* src) {
    asm volatile("cp.async.cg.shared.global [%0], [%1], 16;" :: "r"(dst), "l"(src));
}
__device__ __forceinline__ void cp_commit() {
    asm volatile("cp.async.commit_group;" ::: "memory");
}
template <int N>
__device__ __forceinline__ void cp_wait() {
    asm volatile("cp.async.wait_group %0;" :: "n"(N) : "memory");
}
__device__ __forceinline__ void ldsm_x4(uint32_t* r, uint32_t a) {
    asm volatile("ldmatrix.sync.aligned.m8n8.x4.shared.b16 {%0,%1,%2,%3}, [%4];"
                 : "=r"(r[0]), "=r"(r[1]), "=r"(r[2]), "=r"(r[3]) : "r"(a));
}
__device__ __forceinline__ void ldsm_x4t(uint32_t* r, uint32_t a) {
    asm volatile("ldmatrix.sync.aligned.m8n8.x4.trans.shared.b16 {%0,%1,%2,%3}, [%4];"
                 : "=r"(r[0]), "=r"(r[1]), "=r"(r[2]), "=r"(r[3]) : "r"(a));
}
__device__ __forceinline__ void ldsm_x2(uint32_t* r, uint32_t a) {
    asm volatile("ldmatrix.sync.aligned.m8n8.x2.shared.b16 {%0,%1}, [%2];"
                 : "=r"(r[0]), "=r"(r[1]) : "r"(a));
}
__device__ __forceinline__ void mma16816(float* d, const uint32_t* a, const uint32_t* b) {
    asm volatile(
        "mma.sync.aligned.m16n8k16.row.col.f32.bf16.bf16.f32 "
        "{%0,%1,%2,%3}, {%4,%5,%6,%7}, {%8,%9}, {%0,%1,%2,%3};"
        : "+f"(d[0]), "+f"(d[1]), "+f"(d[2]), "+f"(d[3])
        : "r"(a[0]), "r"(a[1]), "r"(a[2]), "r"(a[3]), "r"(b[0]), "r"(b[1]));
}
// split two fp32 into packed bf16 hi/lo pairs (low element in low 16 bits)
__device__ __forceinline__ void split_pack(float p0, float p1, uint32_t& hi, uint32_t& lo) {
    __nv_bfloat16 h0 = __float2bfloat16_rn(p0), h1 = __float2bfloat16_rn(p1);
    float f0 = __bfloat162float(h0), f1 = __bfloat162float(h1);
    __nv_bfloat16 l0 = __float2bfloat16_rn(p0 - f0), l1 = __float2bfloat16_rn(p1 - f1);
    hi = (uint32_t)__bfloat16_as_ushort(h0) | ((uint32_t)__bfloat16_as_ushort(h1) << 16);
    lo = (uint32_t)__bfloat16_as_ushort(l0) | ((uint32_t)__bfloat16_as_ushort(l1) << 16);
}

// ---------------------------------------------------------------------------
// Kernel: split fp32 -> bf16 hi/lo
// ---------------------------------------------------------------------------
__global__ __launch_bounds__(256) void convert_split(const float* __restrict__ src,
                                                     __nv_bfloat16* __restrict__ hi,
                                                     __nv_bfloat16* __restrict__ lo,
                                                     int n4)
{
    int i = blockIdx.x * 256 + threadIdx.x;
    if (i >= n4) return;
    float4 v = *(const float4*)(src + i * 4);
    __nv_bfloat16 h[4], l[4];
    float vv[4] = {v.x, v.y, v.z, v.w};
    #pragma unroll
    for (int k = 0; k < 4; k++) {
        h[k] = __float2bfloat16_rn(vv[k]);
        l[k] = __float2bfloat16_rn(vv[k] - __bfloat162float(h[k]));
    }
    *(uint2*)(hi + i * 4) = *(uint2*)h;
    *(uint2*)(lo + i * 4) = *(uint2*)l;
}

// ---------------------------------------------------------------------------
// Kernel: fold LoRA into weights, output split bf16 hi/lo
// ---------------------------------------------------------------------------
__global__ __launch_bounds__(256) void fold_lora(
    const float* __restrict__ Wqkv, const float* __restrict__ Bq, const float* __restrict__ Aq,
    const float* __restrict__ Wproj, const float* __restrict__ Bp, const float* __restrict__ Ap)
{
    int idx = blockIdx.x * 256 + threadIdx.x;
    const int n1 = N1_ * E_;
    float val; __nv_bfloat16* hp; __nv_bfloat16* lp; int j;
    if (idx < n1) {
        int o = idx / E_, e = idx - o * E_;
        float acc = 0.f;
        #pragma unroll
        for (int r = 0; r < R_; r++) acc += Bq[o * R_ + r] * Aq[r * E_ + e];
        val = Wqkv[idx] + SCALING_ * acc;
        hp = g_wqhi; lp = g_wqlo; j = idx;
    } else if (idx < n1 + E_ * E_) {
        j = idx - n1;
        int o = j / E_, e = j - o * E_;
        float acc = 0.f;
        #pragma unroll
        for (int r = 0; r < R_; r++) acc += Bp[o * R_ + r] * Ap[r * E_ + e];
        val = Wproj[j] + SCALING_ * acc;
        hp = g_wphi; lp = g_wplo;
    } else return;
    __nv_bfloat16 h = __float2bfloat16_rn(val);
    hp[j] = h;
    lp[j] = __float2bfloat16_rn(val - __bfloat162float(h));
}

// ---------------------------------------------------------------------------
// Kernel: bf16x3 GEMM via mma.sync.
// Output: either fp32 C (+bias) or split bf16 (Chi/Clo).
// ---------------------------------------------------------------------------
#define KC_      32
#define TS_      40
#define TILE_B_  (128 * TS_ * 2)
#define BUF_B_   (4 * TILE_B_)
#define GM_SMEM  (2 * BUF_B_)

__device__ __forceinline__ void gm_load(uint32_t bufu,
                                        const __nv_bfloat16* a0, const __nv_bfloat16* a1,
                                        const __nv_bfloat16* w0, const __nv_bfloat16* w1,
                                        int c, int tid)
{
    const __nv_bfloat16* sp[4] = {a0 + c * KC_, a1 + c * KC_, w0 + c * KC_, w1 + c * KC_};
    #pragma unroll
    for (int t = 0; t < 4; t++) {
        #pragma unroll
        for (int i = 0; i < 2; i++) {
            int idx = tid + 256 * i;
            int row = idx >> 2, q = idx & 3;
            cp16(bufu + t * TILE_B_ + row * (TS_ * 2) + q * 16,
                 sp[t] + (size_t)row * K_ + q * 8);
        }
    }
    cp_commit();
}

__global__ __launch_bounds__(256, 2) void gemm_bf16x3(
    const __nv_bfloat16* __restrict__ Ahi, const __nv_bfloat16* __restrict__ Alo,
    const __nv_bfloat16* __restrict__ Whi, const __nv_bfloat16* __restrict__ Wlo,
    const float* __restrict__ bias, float* __restrict__ C,
    __nv_bfloat16* __restrict__ Chi, __nv_bfloat16* __restrict__ Clo, int N)
{
    extern __shared__ char smc[];
    const uint32_t sbase = smem_u32(smc);

    const int tid  = threadIdx.x;
    const int lane = tid & 31;
    const int warp = tid >> 5;
    const int wm   = warp >> 2;
    const int wn   = warp & 3;

    const __nv_bfloat16* a0 = Ahi + (size_t)blockIdx.y * 128 * K_;
    const __nv_bfloat16* a1 = Alo + (size_t)blockIdx.y * 128 * K_;
    const __nv_bfloat16* w0 = Whi + (size_t)blockIdx.x * 128 * K_;
    const __nv_bfloat16* w1 = Wlo + (size_t)blockIdx.x * 128 * K_;

    const uint32_t laneA = (uint32_t)(((lane & 15) * TS_ + (lane >> 4) * 8) * 2);
    const uint32_t laneB = (uint32_t)(((lane & 7) * TS_ + ((lane >> 3) & 1) * 8) * 2);

    float acc[4][4][4];
    #pragma unroll
    for (int i = 0; i < 4; i++)
        #pragma unroll
        for (int j = 0; j < 4; j++)
            #pragma unroll
            for (int k = 0; k < 4; k++) acc[i][j][k] = 0.f;

    gm_load(sbase,          a0, a1, w0, w1, 0, tid);
    gm_load(sbase + BUF_B_, a0, a1, w0, w1, 1, tid);

    const int nchunks = K_ / KC_;
    #pragma unroll 1
    for (int c = 0; c < nchunks; c++) {
        cp_wait<1>();
        __syncthreads();

        const uint32_t bu   = sbase + (c & 1) * BUF_B_;
        const uint32_t aHiB = bu + (uint32_t)((wm * 64) * TS_ * 2) + laneA;
        const uint32_t aLoB = aHiB + TILE_B_;
        const uint32_t bHiB = bu + 2 * TILE_B_ + (uint32_t)((wn * 32) * TS_ * 2) + laneB;
        const uint32_t bLoB = bHiB + TILE_B_;

        #pragma unroll
        for (int ks = 0; ks < 2; ks++) {
            const uint32_t ko = ks * 32;
            uint32_t Bh[4][2], Bl[4][2];
            #pragma unroll
            for (int nt = 0; nt < 4; nt++) {
                ldsm_x2(Bh[nt], bHiB + nt * (8 * TS_ * 2) + ko);
                ldsm_x2(Bl[nt], bLoB + nt * (8 * TS_ * 2) + ko);
            }
            #pragma unroll
            for (int mt = 0; mt < 4; mt++) {
                uint32_t Ah[4], Al[4];
                ldsm_x4(Ah, aHiB + mt * (16 * TS_ * 2) + ko);
                ldsm_x4(Al, aLoB + mt * (16 * TS_ * 2) + ko);
                #pragma unroll
                for (int nt = 0; nt < 4; nt++) {
                    mma16816(acc[mt][nt], Ah, Bh[nt]);
                    mma16816(acc[mt][nt], Al, Bh[nt]);
                    mma16816(acc[mt][nt], Ah, Bl[nt]);
                }
            }
        }
        __syncthreads();
        if (c + 2 < nchunks)
            gm_load(sbase + (c & 1) * BUF_B_, a0, a1, w0, w1, c + 2, tid);
    }

    const int g  = lane >> 2;
    const int cq = (lane & 3) * 2;
    #pragma unroll
    for (int mt = 0; mt < 4; mt++) {
        const int row = blockIdx.y * 128 + wm * 64 + mt * 16 + g;
        #pragma unroll
        for (int nt = 0; nt < 4; nt++) {
            const int col = blockIdx.x * 128 + wn * 32 + nt * 8 + cq;
            if (Chi) {
                uint32_t h0, l0, h1, l1;
                split_pack(acc[mt][nt][0], acc[mt][nt][1], h0, l0);
                split_pack(acc[mt][nt][2], acc[mt][nt][3], h1, l1);
                *(uint32_t*)(Chi + (size_t)row * N + col)       = h0;
                *(uint32_t*)(Clo + (size_t)row * N + col)       = l0;
                *(uint32_t*)(Chi + (size_t)(row + 8) * N + col) = h1;
                *(uint32_t*)(Clo + (size_t)(row + 8) * N + col) = l1;
            } else {
                float b0 = 0.f, b1 = 0.f;
                if (bias) { b0 = bias[col]; b1 = bias[col + 1]; }
                *(float2*)(C + (size_t)row * N + col) =
                    make_float2(acc[mt][nt][0] + b0, acc[mt][nt][1] + b1);
                *(float2*)(C + (size_t)(row + 8) * N + col) =
                    make_float2(acc[mt][nt][2] + b0, acc[mt][nt][3] + b1);
            }
        }
    }
}

// ---------------------------------------------------------------------------
// Kernel: causal flash attention, bf16x3 mma.sync.
// BQ=128 (8 warps x 16 q-rows), BK=64 key tiles, double-buffered K/V hi/lo.
// smem rows stride 72 bf16 (144B = 36 banks -> conflict-free ldmatrix phases).
// ---------------------------------------------------------------------------
#define FH_S    72
#define FQ_B    (128 * FH_S * 2)        // 18432 B per Q array
#define FT_B    (64 * FH_S * 2)         // 9216 B per K/V tile
#define FBUF_B  (4 * FT_B)              // Kh|Kl|Vh|Vl
#define FM_SMEM (2 * FQ_B + 2 * FBUF_B) // 110592 B

__device__ __forceinline__ void fa_load_kv(uint32_t bufu,
                                           const __nv_bfloat16* kh, const __nv_bfloat16* kl,
                                           const __nv_bfloat16* vh, const __nv_bfloat16* vl,
                                           int k0, int tid)
{
    const __nv_bfloat16* sp[4] = {kh, kl, vh, vl};
    #pragma unroll
    for (int a = 0; a < 4; a++) {
        #pragma unroll
        for (int i = 0; i < 2; i++) {
            int c = tid + 256 * i;            // 0..511
            int row = c >> 3, col = (c & 7) * 8;
            cp16(bufu + a * FT_B + (row * FH_S + col) * 2,
                 sp[a] + (size_t)(k0 + row) * N1_ + col);
        }
    }
    cp_commit();
}

__global__ __launch_bounds__(256, 2) void flash_mma(
    const __nv_bfloat16* __restrict__ qvh, const __nv_bfloat16* __restrict__ qvl)
{
    extern __shared__ char smf[];
    const uint32_t sbase = smem_u32(smf);
    const uint32_t QH = sbase, QL = sbase + FQ_B;
    const uint32_t BUF0 = sbase + 2 * FQ_B;

    const int tid  = threadIdx.x;
    const int lane = tid & 31;
    const int warp = tid >> 5;
    const int b    = blockIdx.y >> 4;
    const int h    = blockIdx.y & 15;
    const int qt   = blockIdx.x;
    const int q0   = qt * 128;

    const __nv_bfloat16* qbh = qvh + (size_t)(b * S_ + q0) * N1_ + h * D_;
    const __nv_bfloat16* qbl = qvl + (size_t)(b * S_ + q0) * N1_ + h * D_;
    const __nv_bfloat16* kbh = qvh + (size_t)(b * S_) * N1_ + E_ + h * D_;
    const __nv_bfloat16* kbl = qvl + (size_t)(b * S_) * N1_ + E_ + h * D_;
    const __nv_bfloat16* vbh = kbh + E_;
    const __nv_bfloat16* vbl = kbl + E_;

    // ---- load Q hi/lo (group 0) ----
    #pragma unroll
    for (int i = 0; i < 4; i++) {
        int c = tid + 256 * i;                // 0..1023
        int row = c >> 3, col = (c & 7) * 8;
        cp16(QH + (row * FH_S + col) * 2, qbh + (size_t)row * N1_ + col);
    }
    #pragma unroll
    for (int i = 0; i < 4; i++) {
        int c = tid + 256 * i;
        int row = c >> 3, col = (c & 7) * 8;
        cp16(QL + (row * FH_S + col) * 2, qbl + (size_t)row * N1_ + col);
    }
    cp_commit();

    const int ntiles = 2 * qt + 2;
    fa_load_kv(BUF0, kbh, kbl, vbh, vbl, 0, tid);
    if (ntiles > 1) fa_load_kv(BUF0 + FBUF_B, kbh, kbl, vbh, vbl, 64, tid);
    else cp_commit();

    // fragment geometry
    const int g  = lane >> 2;
    const int cq = (lane & 3) * 2;
    const uint32_t laneAq = QH + (uint32_t)(((warp * 16 + (lane & 15)) * FH_S + (lane >> 4) * 8) * 2);
    const uint32_t laneK  = (uint32_t)((((lane >> 4) * 8 + (lane & 7)) * FH_S + ((lane >> 3) & 1) * 8) * 2);
    const uint32_t laneV  = (uint32_t)(((((lane >> 3) & 1) * 8 + (lane & 7)) * FH_S + (lane >> 4) * 8) * 2);

    float oacc[8][4];
    float mrow[2] = {-1e30f, -1e30f}, lrow[2] = {0.f, 0.f};
    #pragma unroll
    for (int i = 0; i < 8; i++)
        #pragma unroll
        for (int j = 0; j < 4; j++) oacc[i][j] = 0.f;

    #pragma unroll 1
    for (int t = 0; t < ntiles; t++) {
        cp_wait<1>();
        __syncthreads();
        const uint32_t bufu = BUF0 + (t & 1) * FBUF_B;

        // ---- S = Q K^T (hi*hi + lo*hi + hi*lo) ----
        float sacc[8][4];
        #pragma unroll
        for (int i = 0; i < 8; i++)
            #pragma unroll
            for (int j = 0; j < 4; j++) sacc[i][j] = 0.f;

        #pragma unroll
        for (int ks = 0; ks < 4; ks++) {
            uint32_t Ah[4], Al[4];
            ldsm_x4(Ah, laneAq + ks * 32);
            ldsm_x4(Al, laneAq + FQ_B + ks * 32);
            #pragma unroll
            for (int np = 0; np < 4; np++) {
                uint32_t Bh[4], Bl[4];
                const uint32_t ka = bufu + laneK + np * (16 * FH_S * 2) + ks * 32;
                ldsm_x4(Bh, ka);
                ldsm_x4(Bl, ka + FT_B);
                mma16816(sacc[2 * np],     Ah, &Bh[0]);
                mma16816(sacc[2 * np],     Al, &Bh[0]);
                mma16816(sacc[2 * np],     Ah, &Bl[0]);
                mma16816(sacc[2 * np + 1], Ah, &Bh[2]);
                mma16816(sacc[2 * np + 1], Al, &Bh[2]);
                mma16816(sacc[2 * np + 1], Ah, &Bl[2]);
            }
        }

        // ---- scale + causal mask ----
        #pragma unroll
        for (int nt = 0; nt < 8; nt++)
            #pragma unroll
            for (int c = 0; c < 4; c++) sacc[nt][c] *= SCALE_;
        if (t >= 2 * qt) {
            const int k0 = t * 64;
            #pragma unroll
            for (int nt = 0; nt < 8; nt++)
                #pragma unroll
                for (int c = 0; c < 4; c++) {
                    int colg = k0 + nt * 8 + cq + (c & 1);
                    int rowg = q0 + warp * 16 + g + (c >> 1) * 8;
                    if (colg > rowg) sacc[nt][c] = -1e30f;
                }
        }

        // ---- online softmax (2 rows per thread) ----
        #pragma unroll
        for (int r = 0; r < 2; r++) {
            float mx = -1e30f;
            #pragma unroll
            for (int nt = 0; nt < 8; nt++)
                mx = fmaxf(mx, fmaxf(sacc[nt][2 * r], sacc[nt][2 * r + 1]));
            mx = fmaxf(mx, __shfl_xor_sync(0xffffffffu, mx, 1));
            mx = fmaxf(mx, __shfl_xor_sync(0xffffffffu, mx, 2));
            const float mnew = fmaxf(mrow[r], mx);
            const float corr = __expf(mrow[r] - mnew);
            float rs = 0.f;
            #pragma unroll
            for (int nt = 0; nt < 8; nt++) {
                float p0 = __expf(sacc[nt][2 * r]     - mnew);
                float p1 = __expf(sacc[nt][2 * r + 1] - mnew);
                sacc[nt][2 * r] = p0; sacc[nt][2 * r + 1] = p1;
                rs += p0 + p1;
            }
            rs += __shfl_xor_sync(0xffffffffu, rs, 1);
            rs += __shfl_xor_sync(0xffffffffu, rs, 2);
            lrow[r] = lrow[r] * corr + rs;
            mrow[r] = mnew;
            #pragma unroll
            for (int dn = 0; dn < 8; dn++) {
                oacc[dn][2 * r]     *= corr;
                oacc[dn][2 * r + 1] *= corr;
            }
        }

        // ---- O += P V (P converts in-register to A fragments) ----
        #pragma unroll
        for (int np = 0; np < 4; np++) {
            uint32_t Ph[4], Pl[4];
            split_pack(sacc[2 * np][0],     sacc[2 * np][1],     Ph[0], Pl[0]);
            split_pack(sacc[2 * np][2],     sacc[2 * np][3],     Ph[1], Pl[1]);
            split_pack(sacc[2 * np + 1][0], sacc[2 * np + 1][1], Ph[2], Pl[2]);
            split_pack(sacc[2 * np + 1][2], sacc[2 * np + 1][3], Ph[3], Pl[3]);
            #pragma unroll
            for (int dp = 0; dp < 4; dp++) {
                uint32_t Vh4[4], Vl4[4];
                const uint32_t va = bufu + 2 * FT_B + laneV + np * (16 * FH_S * 2) + dp * 32;
                ldsm_x4t(Vh4, va);
                ldsm_x4t(Vl4, va + FT_B);
                mma16816(oacc[2 * dp],     Ph, &Vh4[0]);
                mma16816(oacc[2 * dp],     Pl, &Vh4[0]);
                mma16816(oacc[2 * dp],     Ph, &Vl4[0]);
                mma16816(oacc[2 * dp + 1], Ph, &Vh4[2]);
                mma16816(oacc[2 * dp + 1], Pl, &Vh4[2]);
                mma16816(oacc[2 * dp + 1], Ph, &Vl4[2]);
            }
        }

        __syncthreads();
        if (t + 2 < ntiles)
            fa_load_kv(BUF0 + (t & 1) * FBUF_B, kbh, kbl, vbh, vbl, (t + 2) * 64, tid);
        else
            cp_commit();
    }

    // ---- normalize + write split hi/lo ----
    const float inv0 = 1.0f / lrow[0];
    const float inv1 = 1.0f / lrow[1];
    const int row0 = q0 + warp * 16 + g;
    #pragma unroll
    for (int dn = 0; dn < 8; dn++) {
        const int col = h * D_ + dn * 8 + cq;
        uint32_t h0, l0, h1, l1;
        split_pack(oacc[dn][0] * inv0, oacc[dn][1] * inv0, h0, l0);
        split_pack(oacc[dn][2] * inv1, oacc[dn][3] * inv1, h1, l1);
        *(uint32_t*)(g_ahi + (size_t)(b * S_ + row0) * E_ + col)     = h0;
        *(uint32_t*)(g_alo + (size_t)(b * S_ + row0) * E_ + col)     = l0;
        *(uint32_t*)(g_ahi + (size_t)(b * S_ + row0 + 8) * E_ + col) = h1;
        *(uint32_t*)(g_alo + (size_t)(b * S_ + row0 + 8) * E_ + col) = l1;
    }
}

// ---------------------------------------------------------------------------
// kernel_launch.  Inputs: x, mask, Wqkv, Wproj, bproj, Aqkv, Bqkv, Aproj, Bproj
// ---------------------------------------------------------------------------
extern "C" void kernel_launch(void* const* d_in, const int* in_sizes, int n_in,
                              void* d_out, int out_size)
{
    const float* x     = (const float*)d_in[0];
    const float* Wqkv  = (const float*)d_in[2];
    const float* Wproj = (const float*)d_in[3];
    const float* bproj = (const float*)d_in[4];
    const float* Aq    = (const float*)d_in[5];
    const float* Bq    = (const float*)d_in[6];
    const float* Ap    = (const float*)d_in[7];
    const float* Bp    = (const float*)d_in[8];
    float* out = (float*)d_out;

    __nv_bfloat16 *xhi, *xlo, *wqhi, *wqlo, *wphi, *wplo, *ahi, *alo, *qvh, *qvl;
    cudaGetSymbolAddress((void**)&xhi,  g_xhi);  cudaGetSymbolAddress((void**)&xlo,  g_xlo);
    cudaGetSymbolAddress((void**)&wqhi, g_wqhi); cudaGetSymbolAddress((void**)&wqlo, g_wqlo);
    cudaGetSymbolAddress((void**)&wphi, g_wphi); cudaGetSymbolAddress((void**)&wplo, g_wplo);
    cudaGetSymbolAddress((void**)&ahi,  g_ahi);  cudaGetSymbolAddress((void**)&alo,  g_alo);
    cudaGetSymbolAddress((void**)&qvh,  g_qvh);  cudaGetSymbolAddress((void**)&qvl,  g_qvl);

    convert_split<<<(M_ * E_ / 4 + 255) / 256, 256>>>(x, xhi, xlo, M_ * E_ / 4);
    const int foldN = N1_ * E_ + E_ * E_;
    fold_lora<<<(foldN + 255) / 256, 256>>>(Wqkv, Bq, Aq, Wproj, Bp, Ap);

    cudaFuncSetAttribute(gemm_bf16x3, cudaFuncAttributeMaxDynamicSharedMemorySize, GM_SMEM);
    // qkv = x @ Wqkv_eff^T  -> split bf16
    gemm_bf16x3<<<dim3(N1_ / 128, M_ / 128), 256, GM_SMEM>>>(
        xhi, xlo, wqhi, wqlo, nullptr, nullptr, qvh, qvl, N1_);

    // tensorized causal flash attention -> split bf16 attn out
    cudaFuncSetAttribute(flash_mma, cudaFuncAttributeMaxDynamicSharedMemorySize, FM_SMEM);
    flash_mma<<<dim3(S_ / 128, B_ * H_), 256, FM_SMEM>>>(qvh, qvl);

    // out = attn @ Wproj_eff^T + bproj  (fp32)
    gemm_bf16x3<<<dim3(E_ / 128, M_ / 128), 256, GM_SMEM>>>(
        ahi, alo, wphi, wplo, bproj, out, nullptr, nullptr, E_);
}

// round 8
// speedup vs baseline: 2.8921x; 1.0414x over previous
#include <cuda_runtime.h>
#include <cuda_bf16.h>
#include <cstdint>

// Problem constants
#define E_   1024
#define H_   16
#define D_   64
#define B_   4
#define S_   2048
#define R_   8
#define M_   (B_*S_)      // 8192
#define N1_  (3*E_)       // 3072
#define K_   1024
#define SCALING_ 2.0f
#define SCALE_   0.125f
#define SC2_     (0.125f * 1.4426950408889634f)   // SCALE * log2(e)

// ---------------------------------------------------------------------------
// Scratch (device globals)
// ---------------------------------------------------------------------------
__device__ __nv_bfloat16  g_qvh[M_ * N1_], g_qvl[M_ * N1_];   // split qkv (GEMM1 out)
__device__ __nv_bfloat16  g_xhi[M_ * E_],  g_xlo[M_ * E_];    // split x
__device__ __nv_bfloat16  g_wqhi[N1_ * E_], g_wqlo[N1_ * E_]; // split folded Wqkv
__device__ __nv_bfloat16  g_wphi[E_ * E_],  g_wplo[E_ * E_];  // split folded Wproj
__device__ __nv_bfloat16  g_ahi[M_ * E_],  g_alo[M_ * E_];    // split attn out

// ---------------------------------------------------------------------------
// PTX helpers (baseline ISA: ldmatrix / mma.sync / cp.async)
// ---------------------------------------------------------------------------
__device__ __forceinline__ uint32_t smem_u32(const void* p) {
    uint32_t a;
    asm("{ .reg .u64 t; cvta.to.shared.u64 t, %1; cvt.u32.u64 %0, t; }" : "=r"(a) : "l"(p));
    return a;
}
__device__ __forceinline__ void cp16(uint32_t dst, const void* src) {
    asm volatile("cp.async.cg.shared.global [%0], [%1], 16;" :: "r"(dst), "l"(src));
}
__device__ __forceinline__ void cp_commit() {
    asm volatile("cp.async.commit_group;" ::: "memory");
}
template <int N>
__device__ __forceinline__ void cp_wait() {
    asm volatile("cp.async.wait_group %0;" :: "n"(N) : "memory");
}
__device__ __forceinline__ void ldsm_x4(uint32_t* r, uint32_t a) {
    asm volatile("ldmatrix.sync.aligned.m8n8.x4.shared.b16 {%0,%1,%2,%3}, [%4];"
                 : "=r"(r[0]), "=r"(r[1]), "=r"(r[2]), "=r"(r[3]) : "r"(a));
}
__device__ __forceinline__ void ldsm_x4t(uint32_t* r, uint32_t a) {
    asm volatile("ldmatrix.sync.aligned.m8n8.x4.trans.shared.b16 {%0,%1,%2,%3}, [%4];"
                 : "=r"(r[0]), "=r"(r[1]), "=r"(r[2]), "=r"(r[3]) : "r"(a));
}
__device__ __forceinline__ void mma16816(float* d, const uint32_t* a, const uint32_t* b) {
    asm volatile(
        "mma.sync.aligned.m16n8k16.row.col.f32.bf16.bf16.f32 "
        "{%0,%1,%2,%3}, {%4,%5,%6,%7}, {%8,%9}, {%0,%1,%2,%3};"
        : "+f"(d[0]), "+f"(d[1]), "+f"(d[2]), "+f"(d[3])
        : "r"(a[0]), "r"(a[1]), "r"(a[2]), "r"(a[3]), "r"(b[0]), "r"(b[1]));
}
__device__ __forceinline__ void split_pack(float p0, float p1, uint32_t& hi, uint32_t& lo) {
    __nv_bfloat16 h0 = __float2bfloat16_rn(p0), h1 = __float2bfloat16_rn(p1);
    float f0 = __bfloat162float(h0), f1 = __bfloat162float(h1);
    __nv_bfloat16 l0 = __float2bfloat16_rn(p0 - f0), l1 = __float2bfloat16_rn(p1 - f1);
    hi = (uint32_t)__bfloat16_as_ushort(h0) | ((uint32_t)__bfloat16_as_ushort(h1) << 16);
    lo = (uint32_t)__bfloat16_as_ushort(l0) | ((uint32_t)__bfloat16_as_ushort(l1) << 16);
}

// ---------------------------------------------------------------------------
// Kernel: split fp32 -> bf16 hi/lo
// ---------------------------------------------------------------------------
__global__ __launch_bounds__(256) void convert_split(const float* __restrict__ src,
                                                     __nv_bfloat16* __restrict__ hi,
                                                     __nv_bfloat16* __restrict__ lo,
                                                     int n4)
{
    int i = blockIdx.x * 256 + threadIdx.x;
    if (i >= n4) return;
    float4 v = *(const float4*)(src + i * 4);
    __nv_bfloat16 h[4], l[4];
    float vv[4] = {v.x, v.y, v.z, v.w};
    #pragma unroll
    for (int k = 0; k < 4; k++) {
        h[k] = __float2bfloat16_rn(vv[k]);
        l[k] = __float2bfloat16_rn(vv[k] - __bfloat162float(h[k]));
    }
    *(uint2*)(hi + i * 4) = *(uint2*)h;
    *(uint2*)(lo + i * 4) = *(uint2*)l;
}

// ---------------------------------------------------------------------------
// Kernel: fold LoRA into weights, output split bf16 hi/lo
// ---------------------------------------------------------------------------
__global__ __launch_bounds__(256) void fold_lora(
    const float* __restrict__ Wqkv, const float* __restrict__ Bq, const float* __restrict__ Aq,
    const float* __restrict__ Wproj, const float* __restrict__ Bp, const float* __restrict__ Ap)
{
    int idx = blockIdx.x * 256 + threadIdx.x;
    const int n1 = N1_ * E_;
    float val; __nv_bfloat16* hp; __nv_bfloat16* lp; int j;
    if (idx < n1) {
        int o = idx / E_, e = idx - o * E_;
        float acc = 0.f;
        #pragma unroll
        for (int r = 0; r < R_; r++) acc += Bq[o * R_ + r] * Aq[r * E_ + e];
        val = Wqkv[idx] + SCALING_ * acc;
        hp = g_wqhi; lp = g_wqlo; j = idx;
    } else if (idx < n1 + E_ * E_) {
        j = idx - n1;
        int o = j / E_, e = j - o * E_;
        float acc = 0.f;
        #pragma unroll
        for (int r = 0; r < R_; r++) acc += Bp[o * R_ + r] * Ap[r * E_ + e];
        val = Wproj[j] + SCALING_ * acc;
        hp = g_wphi; lp = g_wplo;
    } else return;
    __nv_bfloat16 h = __float2bfloat16_rn(val);
    hp[j] = h;
    lp[j] = __float2bfloat16_rn(val - __bfloat162float(h));
}

// ---------------------------------------------------------------------------
// Kernel: bf16x3 GEMM via mma.sync.
// Output: either fp32 C (+bias) or split bf16 (Chi/Clo).
// ---------------------------------------------------------------------------
#define KC_      32
#define TS_      40
#define TILE_B_  (128 * TS_ * 2)
#define BUF_B_   (4 * TILE_B_)
#define GM_SMEM  (2 * BUF_B_)

__device__ __forceinline__ void gm_load(uint32_t bufu,
                                        const __nv_bfloat16* a0, const __nv_bfloat16* a1,
                                        const __nv_bfloat16* w0, const __nv_bfloat16* w1,
                                        int c, int tid)
{
    const __nv_bfloat16* sp[4] = {a0 + c * KC_, a1 + c * KC_, w0 + c * KC_, w1 + c * KC_};
    #pragma unroll
    for (int t = 0; t < 4; t++) {
        #pragma unroll
        for (int i = 0; i < 2; i++) {
            int idx = tid + 256 * i;
            int row = idx >> 2, q = idx & 3;
            cp16(bufu + t * TILE_B_ + row * (TS_ * 2) + q * 16,
                 sp[t] + (size_t)row * K_ + q * 8);
        }
    }
    cp_commit();
}

__global__ __launch_bounds__(256, 2) void gemm_bf16x3(
    const __nv_bfloat16* __restrict__ Ahi, const __nv_bfloat16* __restrict__ Alo,
    const __nv_bfloat16* __restrict__ Whi, const __nv_bfloat16* __restrict__ Wlo,
    const float* __restrict__ bias, float* __restrict__ C,
    __nv_bfloat16* __restrict__ Chi, __nv_bfloat16* __restrict__ Clo, int N)
{
    extern __shared__ char smc[];
    const uint32_t sbase = smem_u32(smc);

    const int tid  = threadIdx.x;
    const int lane = tid & 31;
    const int warp = tid >> 5;
    const int wm   = warp >> 2;
    const int wn   = warp & 3;

    const __nv_bfloat16* a0 = Ahi + (size_t)blockIdx.y * 128 * K_;
    const __nv_bfloat16* a1 = Alo + (size_t)blockIdx.y * 128 * K_;
    const __nv_bfloat16* w0 = Whi + (size_t)blockIdx.x * 128 * K_;
    const __nv_bfloat16* w1 = Wlo + (size_t)blockIdx.x * 128 * K_;

    const uint32_t laneA = (uint32_t)(((lane & 15) * TS_ + (lane >> 4) * 8) * 2);
    // x4 B-fragment layout: lanes 0-15 -> n-rows 0-7 (k0/k8), lanes 16-31 -> n-rows 8-15
    const uint32_t laneB = (uint32_t)((((lane & 7) + ((lane >> 4) << 3)) * TS_ +
                                      (((lane >> 3) & 1) << 3)) * 2);

    float acc[4][4][4];
    #pragma unroll
    for (int i = 0; i < 4; i++)
        #pragma unroll
        for (int j = 0; j < 4; j++)
            #pragma unroll
            for (int k = 0; k < 4; k++) acc[i][j][k] = 0.f;

    gm_load(sbase,          a0, a1, w0, w1, 0, tid);
    gm_load(sbase + BUF_B_, a0, a1, w0, w1, 1, tid);

    const int nchunks = K_ / KC_;
    #pragma unroll 1
    for (int c = 0; c < nchunks; c++) {
        cp_wait<1>();
        __syncthreads();

        const uint32_t bu   = sbase + (c & 1) * BUF_B_;
        const uint32_t aHiB = bu + (uint32_t)((wm * 64) * TS_ * 2) + laneA;
        const uint32_t aLoB = aHiB + TILE_B_;
        const uint32_t bHiB = bu + 2 * TILE_B_ + (uint32_t)((wn * 32) * TS_ * 2) + laneB;
        const uint32_t bLoB = bHiB + TILE_B_;

        #pragma unroll
        for (int ks = 0; ks < 2; ks++) {
            const uint32_t ko = ks * 32;
            uint32_t Bh[2][4], Bl[2][4];    // each x4 covers two n8 fragments
            #pragma unroll
            for (int pr = 0; pr < 2; pr++) {
                ldsm_x4(Bh[pr], bHiB + pr * (16 * TS_ * 2) + ko);
                ldsm_x4(Bl[pr], bLoB + pr * (16 * TS_ * 2) + ko);
            }
            #pragma unroll
            for (int mt = 0; mt < 4; mt++) {
                uint32_t Ah[4], Al[4];
                ldsm_x4(Ah, aHiB + mt * (16 * TS_ * 2) + ko);
                ldsm_x4(Al, aLoB + mt * (16 * TS_ * 2) + ko);
                #pragma unroll
                for (int nt = 0; nt < 4; nt++) {
                    const uint32_t* bh = &Bh[nt >> 1][(nt & 1) * 2];
                    const uint32_t* bl = &Bl[nt >> 1][(nt & 1) * 2];
                    mma16816(acc[mt][nt], Ah, bh);
                    mma16816(acc[mt][nt], Al, bh);
                    mma16816(acc[mt][nt], Ah, bl);
                }
            }
        }
        __syncthreads();
        if (c + 2 < nchunks)
            gm_load(sbase + (c & 1) * BUF_B_, a0, a1, w0, w1, c + 2, tid);
    }

    const int g  = lane >> 2;
    const int cq = (lane & 3) * 2;
    #pragma unroll
    for (int mt = 0; mt < 4; mt++) {
        const int row = blockIdx.y * 128 + wm * 64 + mt * 16 + g;
        #pragma unroll
        for (int nt = 0; nt < 4; nt++) {
            const int col = blockIdx.x * 128 + wn * 32 + nt * 8 + cq;
            if (Chi) {
                uint32_t h0, l0, h1, l1;
                split_pack(acc[mt][nt][0], acc[mt][nt][1], h0, l0);
                split_pack(acc[mt][nt][2], acc[mt][nt][3], h1, l1);
                *(uint32_t*)(Chi + (size_t)row * N + col)       = h0;
                *(uint32_t*)(Clo + (size_t)row * N + col)       = l0;
                *(uint32_t*)(Chi + (size_t)(row + 8) * N + col) = h1;
                *(uint32_t*)(Clo + (size_t)(row + 8) * N + col) = l1;
            } else {
                float b0 = 0.f, b1 = 0.f;
                if (bias) { b0 = bias[col]; b1 = bias[col + 1]; }
                *(float2*)(C + (size_t)row * N + col) =
                    make_float2(acc[mt][nt][0] + b0, acc[mt][nt][1] + b1);
                *(float2*)(C + (size_t)(row + 8) * N + col) =
                    make_float2(acc[mt][nt][2] + b0, acc[mt][nt][3] + b1);
            }
        }
    }
}

// ---------------------------------------------------------------------------
// Kernel: causal flash attention, bf16x3 mma.sync.
// Reversed q-tile scheduling; diagonal fully-masked fragment-tile skipping;
// exp2-domain softmax.
// ---------------------------------------------------------------------------
#define FH_S    72
#define FQ_B    (128 * FH_S * 2)
#define FT_B    (64 * FH_S * 2)
#define FBUF_B  (4 * FT_B)
#define FM_SMEM (2 * FQ_B + 2 * FBUF_B)

__device__ __forceinline__ void fa_load_kv(uint32_t bufu,
                                           const __nv_bfloat16* kh, const __nv_bfloat16* kl,
                                           const __nv_bfloat16* vh, const __nv_bfloat16* vl,
                                           int k0, int tid)
{
    const __nv_bfloat16* sp[4] = {kh, kl, vh, vl};
    #pragma unroll
    for (int a = 0; a < 4; a++) {
        #pragma unroll
        for (int i = 0; i < 2; i++) {
            int c = tid + 256 * i;
            int row = c >> 3, col = (c & 7) * 8;
            cp16(bufu + a * FT_B + (row * FH_S + col) * 2,
                 sp[a] + (size_t)(k0 + row) * N1_ + col);
        }
    }
    cp_commit();
}

__global__ __launch_bounds__(256, 2) void flash_mma(
    const __nv_bfloat16* __restrict__ qvh, const __nv_bfloat16* __restrict__ qvl)
{
    extern __shared__ char smf[];
    const uint32_t sbase = smem_u32(smf);
    const uint32_t QH = sbase, QL = sbase + FQ_B;
    const uint32_t BUF0 = sbase + 2 * FQ_B;

    const int tid  = threadIdx.x;
    const int lane = tid & 31;
    const int warp = tid >> 5;
    const int b    = blockIdx.y >> 4;
    const int h    = blockIdx.y & 15;
    const int qt   = (int)gridDim.x - 1 - (int)blockIdx.x;   // heavy tiles first
    const int q0   = qt * 128;

    const __nv_bfloat16* qbh = qvh + (size_t)(b * S_ + q0) * N1_ + h * D_;
    const __nv_bfloat16* qbl = qvl + (size_t)(b * S_ + q0) * N1_ + h * D_;
    const __nv_bfloat16* kbh = qvh + (size_t)(b * S_) * N1_ + E_ + h * D_;
    const __nv_bfloat16* kbl = qvl + (size_t)(b * S_) * N1_ + E_ + h * D_;
    const __nv_bfloat16* vbh = kbh + E_;
    const __nv_bfloat16* vbl = kbl + E_;

    #pragma unroll
    for (int i = 0; i < 4; i++) {
        int c = tid + 256 * i;
        int row = c >> 3, col = (c & 7) * 8;
        cp16(QH + (row * FH_S + col) * 2, qbh + (size_t)row * N1_ + col);
    }
    #pragma unroll
    for (int i = 0; i < 4; i++) {
        int c = tid + 256 * i;
        int row = c >> 3, col = (c & 7) * 8;
        cp16(QL + (row * FH_S + col) * 2, qbl + (size_t)row * N1_ + col);
    }
    cp_commit();

    const int ntiles = 2 * qt + 2;
    fa_load_kv(BUF0, kbh, kbl, vbh, vbl, 0, tid);
    if (ntiles > 1) fa_load_kv(BUF0 + FBUF_B, kbh, kbl, vbh, vbl, 64, tid);
    else cp_commit();

    const int g  = lane >> 2;
    const int cq = (lane & 3) * 2;
    const uint32_t laneAq = QH + (uint32_t)(((warp * 16 + (lane & 15)) * FH_S + (lane >> 4) * 8) * 2);
    const uint32_t laneK  = (uint32_t)((((lane >> 4) * 8 + (lane & 7)) * FH_S + ((lane >> 3) & 1) * 8) * 2);
    const uint32_t laneV  = (uint32_t)(((((lane >> 3) & 1) * 8 + (lane & 7)) * FH_S + (lane >> 4) * 8) * 2);

    float oacc[8][4];
    float mrow[2] = {-1e30f, -1e30f}, lrow[2] = {0.f, 0.f};
    #pragma unroll
    for (int i = 0; i < 8; i++)
        #pragma unroll
        for (int j = 0; j < 4; j++) oacc[i][j] = 0.f;

    #pragma unroll 1
    for (int t = 0; t < ntiles; t++) {
        cp_wait<1>();
        __syncthreads();
        const uint32_t bufu = BUF0 + (t & 1) * FBUF_B;

        // np-tiles with np >= skipb are fully causal-masked for this warp/tile
        int skipb = 4;
        if (t == 2 * qt)          skipb = warp + 1;
        else if (t == 2 * qt + 1) skipb = warp - 3;
        if (skipb > 4) skipb = 4;
        if (skipb < 0) skipb = 0;

        // ---- S = Q K^T (hi*hi + lo*hi + hi*lo) ----
        float sacc[8][4];
        #pragma unroll
        for (int i = 0; i < 8; i++)
            #pragma unroll
            for (int j = 0; j < 4; j++) sacc[i][j] = 0.f;

        if (skipb > 0) {
            #pragma unroll
            for (int ks = 0; ks < 4; ks++) {
                uint32_t Ah[4], Al[4];
                ldsm_x4(Ah, laneAq + ks * 32);
                ldsm_x4(Al, laneAq + FQ_B + ks * 32);
                #pragma unroll
                for (int np = 0; np < 4; np++) {
                    if (np >= skipb) continue;
                    uint32_t Bh[4], Bl[4];
                    const uint32_t ka = bufu + laneK + np * (16 * FH_S * 2) + ks * 32;
                    ldsm_x4(Bh, ka);
                    ldsm_x4(Bl, ka + FT_B);
                    mma16816(sacc[2 * np],     Ah, &Bh[0]);
                    mma16816(sacc[2 * np],     Al, &Bh[0]);
                    mma16816(sacc[2 * np],     Ah, &Bl[0]);
                    mma16816(sacc[2 * np + 1], Ah, &Bh[2]);
                    mma16816(sacc[2 * np + 1], Al, &Bh[2]);
                    mma16816(sacc[2 * np + 1], Ah, &Bl[2]);
                }
            }
        }

        // ---- scale (log2 domain) + causal mask ----
        #pragma unroll
        for (int nt = 0; nt < 8; nt++)
            #pragma unroll
            for (int c = 0; c < 4; c++) sacc[nt][c] *= SC2_;
        if (t >= 2 * qt) {
            const int k0 = t * 64;
            #pragma unroll
            for (int nt = 0; nt < 8; nt++)
                #pragma unroll
                for (int c = 0; c < 4; c++) {
                    int colg = k0 + nt * 8 + cq + (c & 1);
                    int rowg = q0 + warp * 16 + g + (c >> 1) * 8;
                    if (colg > rowg) sacc[nt][c] = -1e30f;
                }
        }

        // ---- online softmax, exp2 domain (2 rows per thread) ----
        #pragma unroll
        for (int r = 0; r < 2; r++) {
            float mx = -1e30f;
            #pragma unroll
            for (int nt = 0; nt < 8; nt++)
                mx = fmaxf(mx, fmaxf(sacc[nt][2 * r], sacc[nt][2 * r + 1]));
            mx = fmaxf(mx, __shfl_xor_sync(0xffffffffu, mx, 1));
            mx = fmaxf(mx, __shfl_xor_sync(0xffffffffu, mx, 2));
            const float mnew = fmaxf(mrow[r], mx);
            const float corr = exp2f(mrow[r] - mnew);
            float rs = 0.f;
            #pragma unroll
            for (int nt = 0; nt < 8; nt++) {
                float p0 = exp2f(sacc[nt][2 * r]     - mnew);
                float p1 = exp2f(sacc[nt][2 * r + 1] - mnew);
                sacc[nt][2 * r] = p0; sacc[nt][2 * r + 1] = p1;
                rs += p0 + p1;
            }
            rs += __shfl_xor_sync(0xffffffffu, rs, 1);
            rs += __shfl_xor_sync(0xffffffffu, rs, 2);
            lrow[r] = lrow[r] * corr + rs;
            mrow[r] = mnew;
            #pragma unroll
            for (int dn = 0; dn < 8; dn++) {
                oacc[dn][2 * r]     *= corr;
                oacc[dn][2 * r + 1] *= corr;
            }
        }

        // ---- O += P V (skip all-zero P tiles) ----
        #pragma unroll
        for (int np = 0; np < 4; np++) {
            if (np >= skipb) continue;
            uint32_t Ph[4], Pl[4];
            split_pack(sacc[2 * np][0],     sacc[2 * np][1],     Ph[0], Pl[0]);
            split_pack(sacc[2 * np][2],     sacc[2 * np][3],     Ph[1], Pl[1]);
            split_pack(sacc[2 * np + 1][0], sacc[2 * np + 1][1], Ph[2], Pl[2]);
            split_pack(sacc[2 * np + 1][2], sacc[2 * np + 1][3], Ph[3], Pl[3]);
            #pragma unroll
            for (int dp = 0; dp < 4; dp++) {
                uint32_t Vh4[4], Vl4[4];
                const uint32_t va = bufu + 2 * FT_B + laneV + np * (16 * FH_S * 2) + dp * 32;
                ldsm_x4t(Vh4, va);
                ldsm_x4t(Vl4, va + FT_B);
                mma16816(oacc[2 * dp],     Ph, &Vh4[0]);
                mma16816(oacc[2 * dp],     Pl, &Vh4[0]);
                mma16816(oacc[2 * dp],     Ph, &Vl4[0]);
                mma16816(oacc[2 * dp + 1], Ph, &Vh4[2]);
                mma16816(oacc[2 * dp + 1], Pl, &Vh4[2]);
                mma16816(oacc[2 * dp + 1], Ph, &Vl4[2]);
            }
        }

        __syncthreads();
        if (t + 2 < ntiles)
            fa_load_kv(BUF0 + (t & 1) * FBUF_B, kbh, kbl, vbh, vbl, (t + 2) * 64, tid);
        else
            cp_commit();
    }

    // ---- normalize + write split hi/lo ----
    const float inv0 = 1.0f / lrow[0];
    const float inv1 = 1.0f / lrow[1];
    const int row0 = q0 + warp * 16 + g;
    #pragma unroll
    for (int dn = 0; dn < 8; dn++) {
        const int col = h * D_ + dn * 8 + cq;
        uint32_t h0, l0, h1, l1;
        split_pack(oacc[dn][0] * inv0, oacc[dn][1] * inv0, h0, l0);
        split_pack(oacc[dn][2] * inv1, oacc[dn][3] * inv1, h1, l1);
        *(uint32_t*)(g_ahi + (size_t)(b * S_ + row0) * E_ + col)     = h0;
        *(uint32_t*)(g_alo + (size_t)(b * S_ + row0) * E_ + col)     = l0;
        *(uint32_t*)(g_ahi + (size_t)(b * S_ + row0 + 8) * E_ + col) = h1;
        *(uint32_t*)(g_alo + (size_t)(b * S_ + row0 + 8) * E_ + col) = l1;
    }
}

// ---------------------------------------------------------------------------
// kernel_launch.  Inputs: x, mask, Wqkv, Wproj, bproj, Aqkv, Bqkv, Aproj, Bproj
// ---------------------------------------------------------------------------
extern "C" void kernel_launch(void* const* d_in, const int* in_sizes, int n_in,
                              void* d_out, int out_size)
{
    const float* x     = (const float*)d_in[0];
    const float* Wqkv  = (const float*)d_in[2];
    const float* Wproj = (const float*)d_in[3];
    const float* bproj = (const float*)d_in[4];
    const float* Aq    = (const float*)d_in[5];
    const float* Bq    = (const float*)d_in[6];
    const float* Ap    = (const float*)d_in[7];
    const float* Bp    = (const float*)d_in[8];
    float* out = (float*)d_out;

    __nv_bfloat16 *xhi, *xlo, *wqhi, *wqlo, *wphi, *wplo, *ahi, *alo, *qvh, *qvl;
    cudaGetSymbolAddress((void**)&xhi,  g_xhi);  cudaGetSymbolAddress((void**)&xlo,  g_xlo);
    cudaGetSymbolAddress((void**)&wqhi, g_wqhi); cudaGetSymbolAddress((void**)&wqlo, g_wqlo);
    cudaGetSymbolAddress((void**)&wphi, g_wphi); cudaGetSymbolAddress((void**)&wplo, g_wplo);
    cudaGetSymbolAddress((void**)&ahi,  g_ahi);  cudaGetSymbolAddress((void**)&alo,  g_alo);
    cudaGetSymbolAddress((void**)&qvh,  g_qvh);  cudaGetSymbolAddress((void**)&qvl,  g_qvl);

    convert_split<<<(M_ * E_ / 4 + 255) / 256, 256>>>(x, xhi, xlo, M_ * E_ / 4);
    const int foldN = N1_ * E_ + E_ * E_;
    fold_lora<<<(foldN + 255) / 256, 256>>>(Wqkv, Bq, Aq, Wproj, Bp, Ap);

    cudaFuncSetAttribute(gemm_bf16x3, cudaFuncAttributeMaxDynamicSharedMemorySize, GM_SMEM);
    gemm_bf16x3<<<dim3(N1_ / 128, M_ / 128), 256, GM_SMEM>>>(
        xhi, xlo, wqhi, wqlo, nullptr, nullptr, qvh, qvl, N1_);

    cudaFuncSetAttribute(flash_mma, cudaFuncAttributeMaxDynamicSharedMemorySize, FM_SMEM);
    flash_mma<<<dim3(S_ / 128, B_ * H_), 256, FM_SMEM>>>(qvh, qvl);

    gemm_bf16x3<<<dim3(E_ / 128, M_ / 128), 256, GM_SMEM>>>(
        ahi, alo, wphi, wplo, bproj, out, nullptr, nullptr, E_);
}